// round 1
// baseline (speedup 1.0000x reference)
#include <cuda_runtime.h>
#include <math.h>

#define D_MODEL 1024
#define D_FF    1024
#define NE      8
#define NTOK    8192
#define NPAIRS  16384
#define BM 64
#define BN 64
#define BK 16

// Scratch (static device allocations are permitted; no cudaMalloc anywhere).
__device__ float d_act[(size_t)NPAIRS * D_FF];   // 64 MB: SwiGLU activations, row = pair id
__device__ int   d_list[NE * NTOK];              // per-expert pair-id lists
__device__ int   d_cnt[NE];                      // per-expert pair counts
__device__ float d_wgt[NPAIRS];                  // per-pair combine weight
__device__ float d_probs[NTOK * NE];             // per-token softmax probs (for aux loss)

// ---------------------------------------------------------------------------
// Init: zero counters and the dense output region (harness poisons d_out).
// ---------------------------------------------------------------------------
__global__ void init_kernel(float* __restrict__ out) {
    int idx = blockIdx.x * blockDim.x + threadIdx.x;
    if (idx < NE) d_cnt[idx] = 0;
    float4 z = make_float4(0.f, 0.f, 0.f, 0.f);
    float4* o4 = (float4*)out;
    const int n4 = NTOK * D_MODEL / 4;
    for (int i = idx; i < n4; i += gridDim.x * blockDim.x) o4[i] = z;
}

// ---------------------------------------------------------------------------
// Router: one warp per token. logits -> softmax -> stable top-2 -> lists.
// ---------------------------------------------------------------------------
__global__ void router_kernel(const float* __restrict__ x, const float* __restrict__ gw) {
    const int lane = threadIdx.x & 31;
    const int warp = threadIdx.x >> 5;
    const int t = blockIdx.x * (blockDim.x >> 5) + warp;
    if (t >= NTOK) return;

    const float4* xp = (const float4*)(x + (size_t)t * D_MODEL);
    float4 xv[8];
#pragma unroll
    for (int i = 0; i < 8; i++) xv[i] = xp[i * 32 + lane];

    float logit[NE];
#pragma unroll
    for (int e = 0; e < NE; e++) {
        const float4* gp = (const float4*)(gw + e * D_MODEL);
        float s = 0.f;
#pragma unroll
        for (int i = 0; i < 8; i++) {
            float4 g = gp[i * 32 + lane];
            s += xv[i].x * g.x + xv[i].y * g.y + xv[i].z * g.z + xv[i].w * g.w;
        }
#pragma unroll
        for (int o = 16; o > 0; o >>= 1) s += __shfl_xor_sync(0xffffffffu, s, o);
        logit[e] = s;
    }

    if (lane == 0) {
        float m = logit[0];
#pragma unroll
        for (int e = 1; e < NE; e++) m = fmaxf(m, logit[e]);
        float p[NE];
        float sum = 0.f;
#pragma unroll
        for (int e = 0; e < NE; e++) { p[e] = expf(logit[e] - m); sum += p[e]; }
        const float inv = 1.f / sum;
#pragma unroll
        for (int e = 0; e < NE; e++) { p[e] *= inv; d_probs[t * NE + e] = p[e]; }

        // Stable (lowest-index-on-tie) top-2, matching jax.lax.top_k.
        int i0 = 0;
#pragma unroll
        for (int e = 1; e < NE; e++) if (p[e] > p[i0]) i0 = e;
        int i1 = (i0 == 0) ? 1 : 0;
#pragma unroll
        for (int e = 0; e < NE; e++) if (e != i0 && p[e] > p[i1]) i1 = e;

        const float s2 = p[i0] + p[i1];
        const float w0 = p[i0] / s2;
        const float w1 = p[i1] / s2;

        int pos0 = atomicAdd(&d_cnt[i0], 1);
        d_list[i0 * NTOK + pos0] = 2 * t;
        d_wgt[2 * t] = w0;
        int pos1 = atomicAdd(&d_cnt[i1], 1);
        d_list[i1 * NTOK + pos1] = 2 * t + 1;
        d_wgt[2 * t + 1] = w1;
    }
}

// ---------------------------------------------------------------------------
// Aux loss + tokens_per_expert (deterministic fixed-order reduction).
// ---------------------------------------------------------------------------
__global__ void aux_kernel(float* __restrict__ out) {
    __shared__ float s[256][NE];
    const int tid = threadIdx.x;
    float acc[NE];
#pragma unroll
    for (int e = 0; e < NE; e++) acc[e] = 0.f;
    for (int t = tid; t < NTOK; t += 256) {
#pragma unroll
        for (int e = 0; e < NE; e++) acc[e] += d_probs[t * NE + e];
    }
#pragma unroll
    for (int e = 0; e < NE; e++) s[tid][e] = acc[e];
    __syncthreads();
    if (tid == 0) {
        float aux = 0.f;
        for (int e = 0; e < NE; e++) {
            float ps = 0.f;
            for (int i = 0; i < 256; i++) ps += s[i][e];
            float f = (float)d_cnt[e] * (1.f / (float)NPAIRS);
            float P = ps * (1.f / (float)NTOK);
            aux += f * P;
        }
        out[(size_t)NTOK * D_MODEL] = (float)NE * aux;
    }
    if (tid < NE) out[(size_t)NTOK * D_MODEL + 1 + tid] = (float)d_cnt[tid];
}

// ---------------------------------------------------------------------------
// GEMM1: gathered x @ {w_gate, w_up}^T fused, epilogue silu(g)*u -> d_act.
// Tile 64x64x16, 256 threads, 4x4x2 accumulators per thread.
// ---------------------------------------------------------------------------
__global__ __launch_bounds__(256, 2) void gemm1_kernel(const float* __restrict__ x,
                                                       const float* __restrict__ wg,
                                                       const float* __restrict__ wu) {
    const int e = blockIdx.z;
    const int cnt = d_cnt[e];
    const int m0 = blockIdx.x * BM;
    if (m0 >= cnt) return;
    const int n0 = blockIdx.y * BN;

    __shared__ __align__(16) float As[BK][BM + 4];
    __shared__ __align__(16) float Bg[BK][BN + 4];
    __shared__ __align__(16) float Bu[BK][BN + 4];
    __shared__ int plist[BM];

    const int tid = threadIdx.x;
    const int rows = min(BM, cnt - m0);
    if (tid < BM) plist[tid] = (tid < rows) ? d_list[e * NTOK + m0 + tid] : 0;
    __syncthreads();

    const int ra = tid >> 2;            // 0..63
    const int kc = (tid & 3) * 4;       // 0,4,8,12
    const bool va = (ra < rows);
    const float* aptr  = x  + (size_t)(plist[ra] >> 1) * D_MODEL + kc;
    const float* bgptr = wg + (size_t)e * D_FF * D_MODEL + (size_t)(n0 + ra) * D_MODEL + kc;
    const float* buptr = wu + (size_t)e * D_FF * D_MODEL + (size_t)(n0 + ra) * D_MODEL + kc;

    const int tx = tid & 15, ty = tid >> 4;
    float accg[4][4] = {}, accu[4][4] = {};

    for (int k0 = 0; k0 < D_MODEL; k0 += BK) {
        float4 av = va ? *(const float4*)aptr : make_float4(0.f, 0.f, 0.f, 0.f);
        float4 gv = *(const float4*)bgptr;
        float4 uv = *(const float4*)buptr;
        __syncthreads();
        As[kc + 0][ra] = av.x; As[kc + 1][ra] = av.y; As[kc + 2][ra] = av.z; As[kc + 3][ra] = av.w;
        Bg[kc + 0][ra] = gv.x; Bg[kc + 1][ra] = gv.y; Bg[kc + 2][ra] = gv.z; Bg[kc + 3][ra] = gv.w;
        Bu[kc + 0][ra] = uv.x; Bu[kc + 1][ra] = uv.y; Bu[kc + 2][ra] = uv.z; Bu[kc + 3][ra] = uv.w;
        __syncthreads();
#pragma unroll
        for (int k = 0; k < BK; k++) {
            float4 a4 = *(const float4*)&As[k][ty * 4];
            float4 g4 = *(const float4*)&Bg[k][tx * 4];
            float4 u4 = *(const float4*)&Bu[k][tx * 4];
            float ar[4] = {a4.x, a4.y, a4.z, a4.w};
            float gr[4] = {g4.x, g4.y, g4.z, g4.w};
            float ur[4] = {u4.x, u4.y, u4.z, u4.w};
#pragma unroll
            for (int r = 0; r < 4; r++)
#pragma unroll
                for (int c = 0; c < 4; c++) {
                    accg[r][c] += ar[r] * gr[c];
                    accu[r][c] += ar[r] * ur[c];
                }
        }
        aptr += BK; bgptr += BK; buptr += BK;
    }

#pragma unroll
    for (int r = 0; r < 4; r++) {
        const int m = ty * 4 + r;
        if (m < rows) {
            const int pid = plist[m];
            float4 o;
            float g, u;
            g = accg[r][0]; u = accu[r][0]; o.x = (g / (1.f + expf(-g))) * u;
            g = accg[r][1]; u = accu[r][1]; o.y = (g / (1.f + expf(-g))) * u;
            g = accg[r][2]; u = accu[r][2]; o.z = (g / (1.f + expf(-g))) * u;
            g = accg[r][3]; u = accu[r][3]; o.w = (g / (1.f + expf(-g))) * u;
            *(float4*)(d_act + (size_t)pid * D_FF + n0 + tx * 4) = o;
        }
    }
}

// ---------------------------------------------------------------------------
// GEMM2: gathered act @ w_down^T, weighted atomicAdd scatter into out.
// Exactly 2 commutative adds per output element -> bitwise deterministic.
// ---------------------------------------------------------------------------
__global__ __launch_bounds__(256, 2) void gemm2_kernel(const float* __restrict__ wd,
                                                       float* __restrict__ out) {
    const int e = blockIdx.z;
    const int cnt = d_cnt[e];
    const int m0 = blockIdx.x * BM;
    if (m0 >= cnt) return;
    const int n0 = blockIdx.y * BN;

    __shared__ __align__(16) float As[BK][BM + 4];
    __shared__ __align__(16) float Bs[BK][BN + 4];
    __shared__ int plist[BM];

    const int tid = threadIdx.x;
    const int rows = min(BM, cnt - m0);
    if (tid < BM) plist[tid] = (tid < rows) ? d_list[e * NTOK + m0 + tid] : 0;
    __syncthreads();

    const int ra = tid >> 2;
    const int kc = (tid & 3) * 4;
    const bool va = (ra < rows);
    const float* aptr = d_act + (size_t)plist[ra] * D_FF + kc;
    const float* bptr = wd + (size_t)e * D_MODEL * D_FF + (size_t)(n0 + ra) * D_FF + kc;

    const int tx = tid & 15, ty = tid >> 4;
    float acc[4][4] = {};

    for (int k0 = 0; k0 < D_FF; k0 += BK) {
        float4 av = va ? *(const float4*)aptr : make_float4(0.f, 0.f, 0.f, 0.f);
        float4 bv = *(const float4*)bptr;
        __syncthreads();
        As[kc + 0][ra] = av.x; As[kc + 1][ra] = av.y; As[kc + 2][ra] = av.z; As[kc + 3][ra] = av.w;
        Bs[kc + 0][ra] = bv.x; Bs[kc + 1][ra] = bv.y; Bs[kc + 2][ra] = bv.z; Bs[kc + 3][ra] = bv.w;
        __syncthreads();
#pragma unroll
        for (int k = 0; k < BK; k++) {
            float4 a4 = *(const float4*)&As[k][ty * 4];
            float4 b4 = *(const float4*)&Bs[k][tx * 4];
            float ar[4] = {a4.x, a4.y, a4.z, a4.w};
            float br[4] = {b4.x, b4.y, b4.z, b4.w};
#pragma unroll
            for (int r = 0; r < 4; r++)
#pragma unroll
                for (int c = 0; c < 4; c++) acc[r][c] += ar[r] * br[c];
        }
        aptr += BK; bptr += BK;
    }

#pragma unroll
    for (int r = 0; r < 4; r++) {
        const int m = ty * 4 + r;
        if (m < rows) {
            const int pid = plist[m];
            const float w = d_wgt[pid];
            const int tok = pid >> 1;
            float* op = out + (size_t)tok * D_MODEL + n0 + tx * 4;
            atomicAdd(op + 0, w * acc[r][0]);
            atomicAdd(op + 1, w * acc[r][1]);
            atomicAdd(op + 2, w * acc[r][2]);
            atomicAdd(op + 3, w * acc[r][3]);
        }
    }
}

// ---------------------------------------------------------------------------
// Launch (graph-capturable: kernel launches only, default stream ordering).
// ---------------------------------------------------------------------------
extern "C" void kernel_launch(void* const* d_in, const int* in_sizes, int n_in,
                              void* d_out, int out_size) {
    const float* x  = (const float*)d_in[0];
    const float* gw = (const float*)d_in[1];
    const float* wg = (const float*)d_in[2];
    const float* wu = (const float*)d_in[3];
    const float* wd = (const float*)d_in[4];
    float* out = (float*)d_out;

    init_kernel<<<2048, 256>>>(out);
    router_kernel<<<NTOK / 8, 256>>>(x, gw);
    aux_kernel<<<1, 256>>>(out);
    gemm1_kernel<<<dim3(128, 16, 8), 256>>>(x, wg, wu);
    gemm2_kernel<<<dim3(128, 16, 8), 256>>>(wd, out);
}

// round 3
// speedup vs baseline: 2.3036x; 2.3036x over previous
#include <cuda_runtime.h>
#include <cuda_bf16.h>
#include <math.h>
#include <stdint.h>

#define D_MODEL 1024
#define D_FF    1024
#define NE      8
#define NTOK    8192
#define NPAIRS  16384
#define BM      128
#define BN      128
#define BK      32
#define STAGES  3
#define NKT     (D_MODEL / BK)   // 32 k-tiles

// ---------------------------------------------------------------------------
// Static scratch
// ---------------------------------------------------------------------------
__device__ __nv_bfloat16 d_x_h[(size_t)NTOK * D_MODEL];
__device__ __nv_bfloat16 d_x_l[(size_t)NTOK * D_MODEL];
__device__ __nv_bfloat16 d_wg_h[(size_t)NE * D_FF * D_MODEL];
__device__ __nv_bfloat16 d_wg_l[(size_t)NE * D_FF * D_MODEL];
__device__ __nv_bfloat16 d_wu_h[(size_t)NE * D_FF * D_MODEL];
__device__ __nv_bfloat16 d_wu_l[(size_t)NE * D_FF * D_MODEL];
__device__ __nv_bfloat16 d_wd_h[(size_t)NE * D_MODEL * D_FF];
__device__ __nv_bfloat16 d_wd_l[(size_t)NE * D_MODEL * D_FF];
__device__ float d_g[(size_t)NPAIRS * D_FF];
__device__ float d_u[(size_t)NPAIRS * D_FF];
__device__ __nv_bfloat16 d_act_h[(size_t)NPAIRS * D_FF];
__device__ __nv_bfloat16 d_act_l[(size_t)NPAIRS * D_FF];
__device__ float d_eo[(size_t)NPAIRS * D_MODEL];
__device__ int   d_list[NE * NTOK];
__device__ int   d_cnt[NE];
__device__ float d_wgt[NPAIRS];
__device__ float d_probs[NTOK * NE];

// ---------------------------------------------------------------------------
// Helpers (all generic-PTX: sm_80-era instructions, compile on compute_103)
// ---------------------------------------------------------------------------
__device__ __forceinline__ uint32_t smem_u32(const void* p) {
    uint32_t a;
    asm("{ .reg .u64 t; cvta.to.shared.u64 t, %1; cvt.u32.u64 %0, t; }" : "=r"(a) : "l"(p));
    return a;
}
__device__ __forceinline__ void cp16(uint32_t dst, const void* src) {
    asm volatile("cp.async.cg.shared.global [%0], [%1], 16;" :: "r"(dst), "l"(src));
}
#define CP_COMMIT() asm volatile("cp.async.commit_group;" ::: "memory")
#define CP_WAIT1()  asm volatile("cp.async.wait_group 1;" ::: "memory")

__device__ __forceinline__ void ldmA(uint32_t r[4], uint32_t addr) {
    asm volatile("ldmatrix.sync.aligned.m8n8.x4.shared.b16 {%0,%1,%2,%3}, [%4];"
                 : "=r"(r[0]), "=r"(r[1]), "=r"(r[2]), "=r"(r[3]) : "r"(addr));
}
__device__ __forceinline__ void ldmB(uint32_t r[2], uint32_t addr) {
    asm volatile("ldmatrix.sync.aligned.m8n8.x2.shared.b16 {%0,%1}, [%2];"
                 : "=r"(r[0]), "=r"(r[1]) : "r"(addr));
}
__device__ __forceinline__ void mma16816(float d[4], const uint32_t a[4], const uint32_t b[2]) {
    asm volatile("mma.sync.aligned.m16n8k16.row.col.f32.bf16.bf16.f32 "
                 "{%0,%1,%2,%3}, {%4,%5,%6,%7}, {%8,%9}, {%0,%1,%2,%3};"
                 : "+f"(d[0]), "+f"(d[1]), "+f"(d[2]), "+f"(d[3])
                 : "r"(a[0]), "r"(a[1]), "r"(a[2]), "r"(a[3]), "r"(b[0]), "r"(b[1]));
}
__device__ __forceinline__ uint32_t pack_bf(__nv_bfloat16 a, __nv_bfloat16 b) {
    return (uint32_t)__bfloat16_as_ushort(a) | ((uint32_t)__bfloat16_as_ushort(b) << 16);
}

// ---------------------------------------------------------------------------
// Init + hi/lo conversion
// ---------------------------------------------------------------------------
__global__ void init_kernel() {
    if (threadIdx.x < NE) d_cnt[threadIdx.x] = 0;
}

__global__ void conv_kernel(const float* __restrict__ in, __nv_bfloat16* __restrict__ hi,
                            __nv_bfloat16* __restrict__ lo, int n4) {
    const float4* in4 = (const float4*)in;
    uint32_t* h2 = (uint32_t*)hi;
    uint32_t* l2 = (uint32_t*)lo;
    for (int i = blockIdx.x * blockDim.x + threadIdx.x; i < n4; i += gridDim.x * blockDim.x) {
        float4 v = in4[i];
        __nv_bfloat16 hx = __float2bfloat16(v.x), hy = __float2bfloat16(v.y);
        __nv_bfloat16 hz = __float2bfloat16(v.z), hw = __float2bfloat16(v.w);
        h2[2 * i + 0] = pack_bf(hx, hy);
        h2[2 * i + 1] = pack_bf(hz, hw);
        l2[2 * i + 0] = pack_bf(__float2bfloat16(v.x - __bfloat162float(hx)),
                                __float2bfloat16(v.y - __bfloat162float(hy)));
        l2[2 * i + 1] = pack_bf(__float2bfloat16(v.z - __bfloat162float(hz)),
                                __float2bfloat16(v.w - __bfloat162float(hw)));
    }
}

// ---------------------------------------------------------------------------
// Router (verbatim from R1 — passed)
// ---------------------------------------------------------------------------
__global__ void router_kernel(const float* __restrict__ x, const float* __restrict__ gw) {
    const int lane = threadIdx.x & 31;
    const int warp = threadIdx.x >> 5;
    const int t = blockIdx.x * (blockDim.x >> 5) + warp;
    if (t >= NTOK) return;

    const float4* xp = (const float4*)(x + (size_t)t * D_MODEL);
    float4 xv[8];
#pragma unroll
    for (int i = 0; i < 8; i++) xv[i] = xp[i * 32 + lane];

    float logit[NE];
#pragma unroll
    for (int e = 0; e < NE; e++) {
        const float4* gp = (const float4*)(gw + e * D_MODEL);
        float s = 0.f;
#pragma unroll
        for (int i = 0; i < 8; i++) {
            float4 g = gp[i * 32 + lane];
            s += xv[i].x * g.x + xv[i].y * g.y + xv[i].z * g.z + xv[i].w * g.w;
        }
#pragma unroll
        for (int o = 16; o > 0; o >>= 1) s += __shfl_xor_sync(0xffffffffu, s, o);
        logit[e] = s;
    }

    if (lane == 0) {
        float m = logit[0];
#pragma unroll
        for (int e = 1; e < NE; e++) m = fmaxf(m, logit[e]);
        float p[NE], sum = 0.f;
#pragma unroll
        for (int e = 0; e < NE; e++) { p[e] = expf(logit[e] - m); sum += p[e]; }
        const float inv = 1.f / sum;
#pragma unroll
        for (int e = 0; e < NE; e++) { p[e] *= inv; d_probs[t * NE + e] = p[e]; }

        int i0 = 0;
#pragma unroll
        for (int e = 1; e < NE; e++) if (p[e] > p[i0]) i0 = e;
        int i1 = (i0 == 0) ? 1 : 0;
#pragma unroll
        for (int e = 0; e < NE; e++) if (e != i0 && p[e] > p[i1]) i1 = e;

        const float s2 = p[i0] + p[i1];
        int pos0 = atomicAdd(&d_cnt[i0], 1);
        d_list[i0 * NTOK + pos0] = 2 * t;
        d_wgt[2 * t] = p[i0] / s2;
        int pos1 = atomicAdd(&d_cnt[i1], 1);
        d_list[i1 * NTOK + pos1] = 2 * t + 1;
        d_wgt[2 * t + 1] = p[i1] / s2;
    }
}

__global__ void aux_kernel(float* __restrict__ out) {
    __shared__ float s[256][NE];
    const int tid = threadIdx.x;
    float acc[NE];
#pragma unroll
    for (int e = 0; e < NE; e++) acc[e] = 0.f;
    for (int t = tid; t < NTOK; t += 256)
#pragma unroll
        for (int e = 0; e < NE; e++) acc[e] += d_probs[t * NE + e];
#pragma unroll
    for (int e = 0; e < NE; e++) s[tid][e] = acc[e];
    __syncthreads();
    if (tid == 0) {
        float aux = 0.f;
        for (int e = 0; e < NE; e++) {
            float ps = 0.f;
            for (int i = 0; i < 256; i++) ps += s[i][e];
            aux += ((float)d_cnt[e] * (1.f / (float)NPAIRS)) * (ps * (1.f / (float)NTOK));
        }
        out[(size_t)NTOK * D_MODEL] = (float)NE * aux;
    }
    if (tid < NE) out[(size_t)NTOK * D_MODEL + 1 + tid] = (float)d_cnt[tid];
}

// ---------------------------------------------------------------------------
// Grouped gather GEMM: C[pid] = gather(A)[pid>>shift] @ B_e^T  (3-term bf16)
// CTA 128x128, BK=32, 3-stage cp.async, warp tile 64x32, mma.sync m16n8k16.
// SMEM: [0..512) plist; stages at 1024 + s*32768: Ah(8K) Al(8K) Bh(8K) Bl(8K)
// ---------------------------------------------------------------------------
#define STG_SZ   32768
#define MMA_SMEM (1024 + STAGES * STG_SZ)

struct MmaArgs {
    const __nv_bfloat16 *Ah, *Al, *Bh, *Bl;
    float* C;
    int shift;
};

__device__ __forceinline__ void issue_stage(int tid, const int* s_plist, int shift,
                                            const __nv_bfloat16* Ah, const __nv_bfloat16* Al,
                                            const __nv_bfloat16* Bh, const __nv_bfloat16* Bl,
                                            int n0, int kt, uint32_t sstage) {
    // per-matrix: 128 rows x 4 chunks(16B) = 512 chunk loads; 256 threads x 2
#pragma unroll
    for (int q = 0; q < 2; q++) {
        const int id = tid + q * 256;
        const int r = id >> 2, c = id & 3;
        const uint32_t sw = (uint32_t)(r * 64 + ((c ^ (r & 3)) << 4));
        const size_t aoff = (size_t)(s_plist[r] >> shift) * (D_MODEL * 2) + kt * 64 + c * 16;
        const size_t boff = (size_t)(n0 + r) * (D_MODEL * 2) + kt * 64 + c * 16;
        cp16(sstage + sw,                 (const char*)Ah + aoff);
        cp16(sstage + 8192 + sw,          (const char*)Al + aoff);
        cp16(sstage + 16384 + sw,         (const char*)Bh + boff);
        cp16(sstage + 24576 + sw,         (const char*)Bl + boff);
    }
}

__global__ __launch_bounds__(256, 1) void mma_kernel(MmaArgs args) {
    const int e = blockIdx.z;
    const int cnt = d_cnt[e];
    const int m0 = blockIdx.x * BM;
    if (m0 >= cnt) return;
    const int n0 = blockIdx.y * BN;

    extern __shared__ __align__(128) char smem[];
    const uint32_t sb = smem_u32(smem);
    const int tid = threadIdx.x;
    const int lane = tid & 31;
    const int w = tid >> 5;
    const int wm = w >> 2;           // 0..1  (64-row slabs)
    const int wn = w & 3;            // 0..3  (32-col slabs)
    const int rows = min(BM, cnt - m0);

    int* s_plist = (int*)smem;
    if (tid < BM) s_plist[tid] = (tid < rows) ? d_list[e * NTOK + m0 + tid] : 0;
    __syncthreads();

    const __nv_bfloat16* Bh = args.Bh + ((size_t)e << 20);
    const __nv_bfloat16* Bl = args.Bl + ((size_t)e << 20);

    // prologue: stages 0,1
    issue_stage(tid, s_plist, args.shift, args.Ah, args.Al, Bh, Bl, n0, 0, sb + 1024);
    CP_COMMIT();
    issue_stage(tid, s_plist, args.shift, args.Ah, args.Al, Bh, Bl, n0, 1, sb + 1024 + STG_SZ);
    CP_COMMIT();

    float d[4][4][4];
#pragma unroll
    for (int i = 0; i < 4; i++)
#pragma unroll
        for (int j = 0; j < 4; j++)
#pragma unroll
            for (int k = 0; k < 4; k++) d[i][j][k] = 0.f;

    const int arow_lo = (lane & 15);
    const int achunk_hi = (lane >> 4);
    const int brow_lo = (lane & 7);
    const int bchunk_hi = ((lane >> 3) & 1);

    for (int kt = 0; kt < NKT; kt++) {
        CP_WAIT1();
        __syncthreads();
        if (kt + 2 < NKT) {
            issue_stage(tid, s_plist, args.shift, args.Ah, args.Al, Bh, Bl, n0,
                        kt + 2, sb + 1024 + ((kt + 2) % STAGES) * STG_SZ);
        }
        CP_COMMIT();

        const uint32_t st = sb + 1024 + (kt % STAGES) * STG_SZ;
#pragma unroll
        for (int ks = 0; ks < 2; ks++) {
            uint32_t ah[4][4], al[4][4], bh[4][2], bl[4][2];
#pragma unroll
            for (int i = 0; i < 4; i++) {
                const int row = wm * 64 + i * 16 + arow_lo;
                const int ch = ks * 2 + achunk_hi;
                const uint32_t off = (uint32_t)(row * 64 + ((ch ^ (row & 3)) << 4));
                ldmA(ah[i], st + off);
                ldmA(al[i], st + 8192 + off);
            }
#pragma unroll
            for (int j = 0; j < 4; j++) {
                const int row = wn * 32 + j * 8 + brow_lo;
                const int ch = ks * 2 + bchunk_hi;
                const uint32_t off = (uint32_t)(row * 64 + ((ch ^ (row & 3)) << 4));
                ldmB(bh[j], st + 16384 + off);
                ldmB(bl[j], st + 24576 + off);
            }
            // term-major: dependent MMAs to same accumulator are 16 apart
#pragma unroll
            for (int i = 0; i < 4; i++)
#pragma unroll
                for (int j = 0; j < 4; j++) mma16816(d[i][j], ah[i], bh[j]);
#pragma unroll
            for (int i = 0; i < 4; i++)
#pragma unroll
                for (int j = 0; j < 4; j++) mma16816(d[i][j], al[i], bh[j]);
#pragma unroll
            for (int i = 0; i < 4; i++)
#pragma unroll
                for (int j = 0; j < 4; j++) mma16816(d[i][j], ah[i], bl[j]);
        }
        __syncthreads();
    }

    // Epilogue: scatter rows via plist into C[pid][n]
    const int r0 = lane >> 2;
    const int c0 = (lane & 3) * 2;
#pragma unroll
    for (int i = 0; i < 4; i++) {
        const int mA = wm * 64 + i * 16 + r0;
        const int mB = mA + 8;
#pragma unroll
        for (int j = 0; j < 4; j++) {
            const int col = n0 + wn * 32 + j * 8 + c0;
            if (mA < rows) {
                float* p = args.C + (size_t)s_plist[mA] * 1024 + col;
                *(float2*)p = make_float2(d[i][j][0], d[i][j][1]);
            }
            if (mB < rows) {
                float* p = args.C + (size_t)s_plist[mB] * 1024 + col;
                *(float2*)p = make_float2(d[i][j][2], d[i][j][3]);
            }
        }
    }
}

// ---------------------------------------------------------------------------
// SiLU: act = silu(g)*u -> bf16 hi/lo
// ---------------------------------------------------------------------------
__global__ void silu_kernel() {
    const float4* g4 = (const float4*)d_g;
    const float4* u4 = (const float4*)d_u;
    uint2* ah = (uint2*)d_act_h;
    uint2* al = (uint2*)d_act_l;
    const int n4 = NPAIRS * D_FF / 4;
    for (int i = blockIdx.x * blockDim.x + threadIdx.x; i < n4; i += gridDim.x * blockDim.x) {
        float4 g = g4[i], u = u4[i];
        float a0 = (g.x / (1.f + __expf(-g.x))) * u.x;
        float a1 = (g.y / (1.f + __expf(-g.y))) * u.y;
        float a2 = (g.z / (1.f + __expf(-g.z))) * u.z;
        float a3 = (g.w / (1.f + __expf(-g.w))) * u.w;
        __nv_bfloat16 h0 = __float2bfloat16(a0), h1 = __float2bfloat16(a1);
        __nv_bfloat16 h2 = __float2bfloat16(a2), h3 = __float2bfloat16(a3);
        ah[i] = make_uint2(pack_bf(h0, h1), pack_bf(h2, h3));
        al[i] = make_uint2(pack_bf(__float2bfloat16(a0 - __bfloat162float(h0)),
                                   __float2bfloat16(a1 - __bfloat162float(h1))),
                           pack_bf(__float2bfloat16(a2 - __bfloat162float(h2)),
                                   __float2bfloat16(a3 - __bfloat162float(h3))));
    }
}

// ---------------------------------------------------------------------------
// Combine: out[t] = w0*eo[2t] + w1*eo[2t+1]
// ---------------------------------------------------------------------------
__global__ void combine_kernel(float* __restrict__ out) {
    const float4* eo4 = (const float4*)d_eo;
    float4* out4 = (float4*)out;
    const int n4 = NTOK * D_MODEL / 4;
    for (int i = blockIdx.x * blockDim.x + threadIdx.x; i < n4; i += gridDim.x * blockDim.x) {
        const int t = i >> 8;
        const int c = i & 255;
        const float w0 = d_wgt[2 * t], w1 = d_wgt[2 * t + 1];
        float4 a = eo4[(size_t)(2 * t) * 256 + c];
        float4 b = eo4[(size_t)(2 * t + 1) * 256 + c];
        out4[i] = make_float4(w0 * a.x + w1 * b.x, w0 * a.y + w1 * b.y,
                              w0 * a.z + w1 * b.z, w0 * a.w + w1 * b.w);
    }
}

// ---------------------------------------------------------------------------
// Launch
// ---------------------------------------------------------------------------
extern "C" void kernel_launch(void* const* d_in, const int* in_sizes, int n_in,
                              void* d_out, int out_size) {
    const float* x  = (const float*)d_in[0];
    const float* gw = (const float*)d_in[1];
    const float* wg = (const float*)d_in[2];
    const float* wu = (const float*)d_in[3];
    const float* wd = (const float*)d_in[4];
    float* out = (float*)d_out;

    cudaFuncSetAttribute(mma_kernel, cudaFuncAttributeMaxDynamicSharedMemorySize, MMA_SMEM);

    __nv_bfloat16 *xh, *xl, *wgh, *wgl, *wuh, *wul, *wdh, *wdl, *acth, *actl;
    float *gptr, *uptr, *eoptr;
    cudaGetSymbolAddress((void**)&xh, d_x_h);   cudaGetSymbolAddress((void**)&xl, d_x_l);
    cudaGetSymbolAddress((void**)&wgh, d_wg_h); cudaGetSymbolAddress((void**)&wgl, d_wg_l);
    cudaGetSymbolAddress((void**)&wuh, d_wu_h); cudaGetSymbolAddress((void**)&wul, d_wu_l);
    cudaGetSymbolAddress((void**)&wdh, d_wd_h); cudaGetSymbolAddress((void**)&wdl, d_wd_l);
    cudaGetSymbolAddress((void**)&acth, d_act_h); cudaGetSymbolAddress((void**)&actl, d_act_l);
    cudaGetSymbolAddress((void**)&gptr, d_g);   cudaGetSymbolAddress((void**)&uptr, d_u);
    cudaGetSymbolAddress((void**)&eoptr, d_eo);

    const int N4 = NTOK * D_MODEL / 4;           // x
    const int W4 = NE * D_FF * D_MODEL / 4;      // each weight tensor

    init_kernel<<<1, 256>>>();
    conv_kernel<<<1184, 256>>>(x,  xh,  xl,  N4);
    conv_kernel<<<1184, 256>>>(wg, wgh, wgl, W4);
    conv_kernel<<<1184, 256>>>(wu, wuh, wul, W4);
    conv_kernel<<<1184, 256>>>(wd, wdh, wdl, W4);
    router_kernel<<<NTOK / 8, 256>>>(x, gw);
    aux_kernel<<<1, 256>>>(out);

    MmaArgs a1g{xh, xl, wgh, wgl, gptr, 1};
    MmaArgs a1u{xh, xl, wuh, wul, uptr, 1};
    MmaArgs a2 {acth, actl, wdh, wdl, eoptr, 0};
    mma_kernel<<<dim3(64, 8, 8), 256, MMA_SMEM>>>(a1g);
    mma_kernel<<<dim3(64, 8, 8), 256, MMA_SMEM>>>(a1u);
    silu_kernel<<<1184, 256>>>();
    mma_kernel<<<dim3(64, 8, 8), 256, MMA_SMEM>>>(a2);
    combine_kernel<<<1184, 256>>>(out);
}

// round 4
// speedup vs baseline: 2.4204x; 1.0507x over previous
#include <cuda_runtime.h>
#include <cuda_bf16.h>
#include <math.h>
#include <stdint.h>

#define D_MODEL 1024
#define D_FF    1024
#define NE      8
#define NTOK    8192
#define NPAIRS  16384
#define BM      128
#define BN      128
#define BK      32
#define STAGES  3
#define NKT     32

// ---------------------------------------------------------------------------
// Static scratch
// ---------------------------------------------------------------------------
__device__ __nv_bfloat16 d_x_h[(size_t)NTOK * D_MODEL];
__device__ __nv_bfloat16 d_x_l[(size_t)NTOK * D_MODEL];
__device__ __nv_bfloat16 d_wg_h[(size_t)NE * D_FF * D_MODEL];
__device__ __nv_bfloat16 d_wg_l[(size_t)NE * D_FF * D_MODEL];
__device__ __nv_bfloat16 d_wu_h[(size_t)NE * D_FF * D_MODEL];
__device__ __nv_bfloat16 d_wu_l[(size_t)NE * D_FF * D_MODEL];
__device__ __nv_bfloat16 d_wd_h[(size_t)NE * D_MODEL * D_FF];
__device__ __nv_bfloat16 d_wd_l[(size_t)NE * D_MODEL * D_FF];
__device__ __nv_bfloat16 d_act_h[(size_t)NPAIRS * D_FF];
__device__ __nv_bfloat16 d_act_l[(size_t)NPAIRS * D_FF];
__device__ int   d_list[NE * NTOK];
__device__ int   d_cnt[NE];
__device__ float d_wgt[NPAIRS];
__device__ float d_probs[NTOK * NE];

// ---------------------------------------------------------------------------
// Helpers (generic PTX only — compiles on compute_103 family target)
// ---------------------------------------------------------------------------
__device__ __forceinline__ uint32_t smem_u32(const void* p) {
    uint32_t a;
    asm("{ .reg .u64 t; cvta.to.shared.u64 t, %1; cvt.u32.u64 %0, t; }" : "=r"(a) : "l"(p));
    return a;
}
__device__ __forceinline__ void cp16(uint32_t dst, const void* src) {
    asm volatile("cp.async.cg.shared.global [%0], [%1], 16;" :: "r"(dst), "l"(src));
}
#define CP_COMMIT() asm volatile("cp.async.commit_group;" ::: "memory")
#define CP_WAIT1()  asm volatile("cp.async.wait_group 1;" ::: "memory")

__device__ __forceinline__ void ldmA(uint32_t r[4], uint32_t addr) {
    asm volatile("ldmatrix.sync.aligned.m8n8.x4.shared.b16 {%0,%1,%2,%3}, [%4];"
                 : "=r"(r[0]), "=r"(r[1]), "=r"(r[2]), "=r"(r[3]) : "r"(addr));
}
__device__ __forceinline__ void ldmB(uint32_t r[2], uint32_t addr) {
    asm volatile("ldmatrix.sync.aligned.m8n8.x2.shared.b16 {%0,%1}, [%2];"
                 : "=r"(r[0]), "=r"(r[1]) : "r"(addr));
}
__device__ __forceinline__ void mma16816(float d[4], const uint32_t a[4], const uint32_t b[2]) {
    asm volatile("mma.sync.aligned.m16n8k16.row.col.f32.bf16.bf16.f32 "
                 "{%0,%1,%2,%3}, {%4,%5,%6,%7}, {%8,%9}, {%0,%1,%2,%3};"
                 : "+f"(d[0]), "+f"(d[1]), "+f"(d[2]), "+f"(d[3])
                 : "r"(a[0]), "r"(a[1]), "r"(a[2]), "r"(a[3]), "r"(b[0]), "r"(b[1]));
}
__device__ __forceinline__ uint32_t pack_bf(__nv_bfloat16 a, __nv_bfloat16 b) {
    return (uint32_t)__bfloat16_as_ushort(a) | ((uint32_t)__bfloat16_as_ushort(b) << 16);
}
__device__ __forceinline__ float silu_mul(float g, float u) {
    return (g / (1.f + __expf(-g))) * u;
}

// ---------------------------------------------------------------------------
// Init: zero counters + output region (harness poisons d_out)
// ---------------------------------------------------------------------------
__global__ void init_kernel(float* __restrict__ out) {
    int idx = blockIdx.x * blockDim.x + threadIdx.x;
    if (idx < NE) d_cnt[idx] = 0;
    float4 z = make_float4(0.f, 0.f, 0.f, 0.f);
    float4* o4 = (float4*)out;
    const int n4 = NTOK * D_MODEL / 4;
    for (int i = idx; i < n4; i += gridDim.x * blockDim.x) o4[i] = z;
}

__global__ void conv_kernel(const float* __restrict__ in, __nv_bfloat16* __restrict__ hi,
                            __nv_bfloat16* __restrict__ lo, int n4) {
    const float4* in4 = (const float4*)in;
    uint32_t* h2 = (uint32_t*)hi;
    uint32_t* l2 = (uint32_t*)lo;
    for (int i = blockIdx.x * blockDim.x + threadIdx.x; i < n4; i += gridDim.x * blockDim.x) {
        float4 v = in4[i];
        __nv_bfloat16 hx = __float2bfloat16(v.x), hy = __float2bfloat16(v.y);
        __nv_bfloat16 hz = __float2bfloat16(v.z), hw = __float2bfloat16(v.w);
        h2[2 * i + 0] = pack_bf(hx, hy);
        h2[2 * i + 1] = pack_bf(hz, hw);
        l2[2 * i + 0] = pack_bf(__float2bfloat16(v.x - __bfloat162float(hx)),
                                __float2bfloat16(v.y - __bfloat162float(hy)));
        l2[2 * i + 1] = pack_bf(__float2bfloat16(v.z - __bfloat162float(hz)),
                                __float2bfloat16(v.w - __bfloat162float(hw)));
    }
}

// ---------------------------------------------------------------------------
// Router + aux (verbatim — passed since R1)
// ---------------------------------------------------------------------------
__global__ void router_kernel(const float* __restrict__ x, const float* __restrict__ gw) {
    const int lane = threadIdx.x & 31;
    const int warp = threadIdx.x >> 5;
    const int t = blockIdx.x * (blockDim.x >> 5) + warp;
    if (t >= NTOK) return;

    const float4* xp = (const float4*)(x + (size_t)t * D_MODEL);
    float4 xv[8];
#pragma unroll
    for (int i = 0; i < 8; i++) xv[i] = xp[i * 32 + lane];

    float logit[NE];
#pragma unroll
    for (int e = 0; e < NE; e++) {
        const float4* gp = (const float4*)(gw + e * D_MODEL);
        float s = 0.f;
#pragma unroll
        for (int i = 0; i < 8; i++) {
            float4 g = gp[i * 32 + lane];
            s += xv[i].x * g.x + xv[i].y * g.y + xv[i].z * g.z + xv[i].w * g.w;
        }
#pragma unroll
        for (int o = 16; o > 0; o >>= 1) s += __shfl_xor_sync(0xffffffffu, s, o);
        logit[e] = s;
    }

    if (lane == 0) {
        float m = logit[0];
#pragma unroll
        for (int e = 1; e < NE; e++) m = fmaxf(m, logit[e]);
        float p[NE], sum = 0.f;
#pragma unroll
        for (int e = 0; e < NE; e++) { p[e] = expf(logit[e] - m); sum += p[e]; }
        const float inv = 1.f / sum;
#pragma unroll
        for (int e = 0; e < NE; e++) { p[e] *= inv; d_probs[t * NE + e] = p[e]; }

        int i0 = 0;
#pragma unroll
        for (int e = 1; e < NE; e++) if (p[e] > p[i0]) i0 = e;
        int i1 = (i0 == 0) ? 1 : 0;
#pragma unroll
        for (int e = 0; e < NE; e++) if (e != i0 && p[e] > p[i1]) i1 = e;

        const float s2 = p[i0] + p[i1];
        int pos0 = atomicAdd(&d_cnt[i0], 1);
        d_list[i0 * NTOK + pos0] = 2 * t;
        d_wgt[2 * t] = p[i0] / s2;
        int pos1 = atomicAdd(&d_cnt[i1], 1);
        d_list[i1 * NTOK + pos1] = 2 * t + 1;
        d_wgt[2 * t + 1] = p[i1] / s2;
    }
}

__global__ void aux_kernel(float* __restrict__ out) {
    __shared__ float s[256][NE];
    const int tid = threadIdx.x;
    float acc[NE];
#pragma unroll
    for (int e = 0; e < NE; e++) acc[e] = 0.f;
    for (int t = tid; t < NTOK; t += 256)
#pragma unroll
        for (int e = 0; e < NE; e++) acc[e] += d_probs[t * NE + e];
#pragma unroll
    for (int e = 0; e < NE; e++) s[tid][e] = acc[e];
    __syncthreads();
    if (tid == 0) {
        float aux = 0.f;
        for (int e = 0; e < NE; e++) {
            float ps = 0.f;
            for (int i = 0; i < 256; i++) ps += s[i][e];
            aux += ((float)d_cnt[e] * (1.f / (float)NPAIRS)) * (ps * (1.f / (float)NTOK));
        }
        out[(size_t)NTOK * D_MODEL] = (float)NE * aux;
    }
    if (tid < NE) out[(size_t)NTOK * D_MODEL + 1 + tid] = (float)d_cnt[tid];
}

// ---------------------------------------------------------------------------
// GEMM1 fused: g = x@wg^T, u = x@wu^T (3-term bf16 each), act = silu(g)*u.
// 512 threads (16 warps, 4x4 warp grid, warp tile 32x32 per matrix).
// Stage (48KB): Ah(8K) Al(8K) Gh(8K) Gl(8K) Uh(8K) Ul(8K); 3 stages.
// ---------------------------------------------------------------------------
#define G1_STG  49152
#define G1_SMEM (1024 + STAGES * G1_STG)

__device__ __forceinline__ void g1_issue(int tid, const int* plist,
                                         const __nv_bfloat16* xh, const __nv_bfloat16* xl,
                                         const __nv_bfloat16* gh, const __nv_bfloat16* gl,
                                         const __nv_bfloat16* uh, const __nv_bfloat16* ul,
                                         int n0, int kt, uint32_t base) {
    const int r = tid >> 2, c = tid & 3;
    const uint32_t sw = (uint32_t)(r * 64 + ((c ^ (r & 3)) << 4));
    const size_t aoff = (size_t)(plist[r] >> 1) * (D_MODEL * 2) + kt * 64 + c * 16;
    const size_t boff = (size_t)(n0 + r) * (D_MODEL * 2) + kt * 64 + c * 16;
    cp16(base + sw,         (const char*)xh + aoff);
    cp16(base + 8192 + sw,  (const char*)xl + aoff);
    cp16(base + 16384 + sw, (const char*)gh + boff);
    cp16(base + 24576 + sw, (const char*)gl + boff);
    cp16(base + 32768 + sw, (const char*)uh + boff);
    cp16(base + 40960 + sw, (const char*)ul + boff);
}

__global__ __launch_bounds__(512, 1) void gemm1_kernel() {
    const int e = blockIdx.z;
    const int cnt = d_cnt[e];
    const int m0 = blockIdx.x * BM;
    if (m0 >= cnt) return;
    const int n0 = blockIdx.y * BN;

    extern __shared__ __align__(128) char smem[];
    const uint32_t sb = smem_u32(smem);
    const int tid = threadIdx.x;
    const int lane = tid & 31;
    const int w = tid >> 5;
    const int wm = w >> 2, wn = w & 3;
    const int rows = min(BM, cnt - m0);

    int* s_plist = (int*)smem;
    if (tid < BM) s_plist[tid] = (tid < rows) ? d_list[e * NTOK + m0 + tid] : 0;
    __syncthreads();

    const __nv_bfloat16* gh = d_wg_h + ((size_t)e << 20);
    const __nv_bfloat16* gl = d_wg_l + ((size_t)e << 20);
    const __nv_bfloat16* uh = d_wu_h + ((size_t)e << 20);
    const __nv_bfloat16* ul = d_wu_l + ((size_t)e << 20);

    g1_issue(tid, s_plist, d_x_h, d_x_l, gh, gl, uh, ul, n0, 0, sb + 1024);
    CP_COMMIT();
    g1_issue(tid, s_plist, d_x_h, d_x_l, gh, gl, uh, ul, n0, 1, sb + 1024 + G1_STG);
    CP_COMMIT();

    float dg[2][4][4], du[2][4][4];
#pragma unroll
    for (int i = 0; i < 2; i++)
#pragma unroll
        for (int j = 0; j < 4; j++)
#pragma unroll
            for (int k = 0; k < 4; k++) { dg[i][j][k] = 0.f; du[i][j][k] = 0.f; }

    for (int kt = 0; kt < NKT; kt++) {
        CP_WAIT1();
        __syncthreads();
        if (kt + 2 < NKT)
            g1_issue(tid, s_plist, d_x_h, d_x_l, gh, gl, uh, ul, n0,
                     kt + 2, sb + 1024 + ((kt + 2) % STAGES) * G1_STG);
        CP_COMMIT();

        const uint32_t st = sb + 1024 + (kt % STAGES) * G1_STG;
#pragma unroll
        for (int ks = 0; ks < 2; ks++) {
            uint32_t ah[2][4], al[2][4];
#pragma unroll
            for (int i = 0; i < 2; i++) {
                const int row = wm * 32 + i * 16 + (lane & 15);
                const int ch = ks * 2 + (lane >> 4);
                const uint32_t off = (uint32_t)(row * 64 + ((ch ^ (row & 3)) << 4));
                ldmA(ah[i], st + off);
                ldmA(al[i], st + 8192 + off);
            }
            {
                uint32_t bh[4][2], bl[4][2];
#pragma unroll
                for (int j = 0; j < 4; j++) {
                    const int row = wn * 32 + j * 8 + (lane & 7);
                    const int ch = ks * 2 + ((lane >> 3) & 1);
                    const uint32_t off = (uint32_t)(row * 64 + ((ch ^ (row & 3)) << 4));
                    ldmB(bh[j], st + 16384 + off);
                    ldmB(bl[j], st + 24576 + off);
                }
#pragma unroll
                for (int i = 0; i < 2; i++)
#pragma unroll
                    for (int j = 0; j < 4; j++) mma16816(dg[i][j], ah[i], bh[j]);
#pragma unroll
                for (int i = 0; i < 2; i++)
#pragma unroll
                    for (int j = 0; j < 4; j++) mma16816(dg[i][j], al[i], bh[j]);
#pragma unroll
                for (int i = 0; i < 2; i++)
#pragma unroll
                    for (int j = 0; j < 4; j++) mma16816(dg[i][j], ah[i], bl[j]);
            }
            {
                uint32_t bh[4][2], bl[4][2];
#pragma unroll
                for (int j = 0; j < 4; j++) {
                    const int row = wn * 32 + j * 8 + (lane & 7);
                    const int ch = ks * 2 + ((lane >> 3) & 1);
                    const uint32_t off = (uint32_t)(row * 64 + ((ch ^ (row & 3)) << 4));
                    ldmB(bh[j], st + 32768 + off);
                    ldmB(bl[j], st + 40960 + off);
                }
#pragma unroll
                for (int i = 0; i < 2; i++)
#pragma unroll
                    for (int j = 0; j < 4; j++) mma16816(du[i][j], ah[i], bh[j]);
#pragma unroll
                for (int i = 0; i < 2; i++)
#pragma unroll
                    for (int j = 0; j < 4; j++) mma16816(du[i][j], al[i], bh[j]);
#pragma unroll
                for (int i = 0; i < 2; i++)
#pragma unroll
                    for (int j = 0; j < 4; j++) mma16816(du[i][j], ah[i], bl[j]);
            }
        }
        __syncthreads();
    }

    // Epilogue: act = silu(g)*u -> bf16 hi/lo, gathered row scatter
    const int r0 = lane >> 2;
    const int c0 = (lane & 3) * 2;
#pragma unroll
    for (int i = 0; i < 2; i++) {
        const int mA = wm * 32 + i * 16 + r0;
        const int mB = mA + 8;
        const int pidA = s_plist[mA & 127];
        const int pidB = s_plist[mB & 127];
#pragma unroll
        for (int j = 0; j < 4; j++) {
            const int col = n0 + wn * 32 + j * 8 + c0;
            if (mA < rows) {
                const float a0 = silu_mul(dg[i][j][0], du[i][j][0]);
                const float a1 = silu_mul(dg[i][j][1], du[i][j][1]);
                const __nv_bfloat16 h0 = __float2bfloat16(a0);
                const __nv_bfloat16 h1 = __float2bfloat16(a1);
                *(uint32_t*)(d_act_h + (size_t)pidA * D_FF + col) = pack_bf(h0, h1);
                *(uint32_t*)(d_act_l + (size_t)pidA * D_FF + col) =
                    pack_bf(__float2bfloat16(a0 - __bfloat162float(h0)),
                            __float2bfloat16(a1 - __bfloat162float(h1)));
            }
            if (mB < rows) {
                const float a0 = silu_mul(dg[i][j][2], du[i][j][2]);
                const float a1 = silu_mul(dg[i][j][3], du[i][j][3]);
                const __nv_bfloat16 h0 = __float2bfloat16(a0);
                const __nv_bfloat16 h1 = __float2bfloat16(a1);
                *(uint32_t*)(d_act_h + (size_t)pidB * D_FF + col) = pack_bf(h0, h1);
                *(uint32_t*)(d_act_l + (size_t)pidB * D_FF + col) =
                    pack_bf(__float2bfloat16(a0 - __bfloat162float(h0)),
                            __float2bfloat16(a1 - __bfloat162float(h1)));
            }
        }
    }
}

// ---------------------------------------------------------------------------
// GEMM2: eo = act @ wd^T (3-term), weighted atomicAdd scatter into out.
// 512 threads, warp tile 32x32. Stage (32KB): Ah Al Bh Bl; 3 stages.
// ---------------------------------------------------------------------------
#define G2_STG  32768
#define G2_SMEM (1024 + STAGES * G2_STG)

__device__ __forceinline__ void g2_issue(int tid, const int* plist,
                                         const __nv_bfloat16* bh, const __nv_bfloat16* bl,
                                         int n0, int kt, uint32_t base) {
    const int r = tid >> 2, c = tid & 3;
    const uint32_t sw = (uint32_t)(r * 64 + ((c ^ (r & 3)) << 4));
    const size_t aoff = (size_t)plist[r] * (D_FF * 2) + kt * 64 + c * 16;
    const size_t boff = (size_t)(n0 + r) * (D_FF * 2) + kt * 64 + c * 16;
    cp16(base + sw,         (const char*)d_act_h + aoff);
    cp16(base + 8192 + sw,  (const char*)d_act_l + aoff);
    cp16(base + 16384 + sw, (const char*)bh + boff);
    cp16(base + 24576 + sw, (const char*)bl + boff);
}

__global__ __launch_bounds__(512, 1) void gemm2_kernel(float* __restrict__ out) {
    const int e = blockIdx.z;
    const int cnt = d_cnt[e];
    const int m0 = blockIdx.x * BM;
    if (m0 >= cnt) return;
    const int n0 = blockIdx.y * BN;

    extern __shared__ __align__(128) char smem[];
    const uint32_t sb = smem_u32(smem);
    const int tid = threadIdx.x;
    const int lane = tid & 31;
    const int w = tid >> 5;
    const int wm = w >> 2, wn = w & 3;
    const int rows = min(BM, cnt - m0);

    int* s_plist = (int*)smem;
    if (tid < BM) s_plist[tid] = (tid < rows) ? d_list[e * NTOK + m0 + tid] : 0;
    __syncthreads();

    const __nv_bfloat16* bh = d_wd_h + ((size_t)e << 20);
    const __nv_bfloat16* bl = d_wd_l + ((size_t)e << 20);

    g2_issue(tid, s_plist, bh, bl, n0, 0, sb + 1024);
    CP_COMMIT();
    g2_issue(tid, s_plist, bh, bl, n0, 1, sb + 1024 + G2_STG);
    CP_COMMIT();

    float dd[2][4][4];
#pragma unroll
    for (int i = 0; i < 2; i++)
#pragma unroll
        for (int j = 0; j < 4; j++)
#pragma unroll
            for (int k = 0; k < 4; k++) dd[i][j][k] = 0.f;

    for (int kt = 0; kt < NKT; kt++) {
        CP_WAIT1();
        __syncthreads();
        if (kt + 2 < NKT)
            g2_issue(tid, s_plist, bh, bl, n0, kt + 2,
                     sb + 1024 + ((kt + 2) % STAGES) * G2_STG);
        CP_COMMIT();

        const uint32_t st = sb + 1024 + (kt % STAGES) * G2_STG;
#pragma unroll
        for (int ks = 0; ks < 2; ks++) {
            uint32_t ah[2][4], al[2][4], fh[4][2], fl[4][2];
#pragma unroll
            for (int i = 0; i < 2; i++) {
                const int row = wm * 32 + i * 16 + (lane & 15);
                const int ch = ks * 2 + (lane >> 4);
                const uint32_t off = (uint32_t)(row * 64 + ((ch ^ (row & 3)) << 4));
                ldmA(ah[i], st + off);
                ldmA(al[i], st + 8192 + off);
            }
#pragma unroll
            for (int j = 0; j < 4; j++) {
                const int row = wn * 32 + j * 8 + (lane & 7);
                const int ch = ks * 2 + ((lane >> 3) & 1);
                const uint32_t off = (uint32_t)(row * 64 + ((ch ^ (row & 3)) << 4));
                ldmB(fh[j], st + 16384 + off);
                ldmB(fl[j], st + 24576 + off);
            }
#pragma unroll
            for (int i = 0; i < 2; i++)
#pragma unroll
                for (int j = 0; j < 4; j++) mma16816(dd[i][j], ah[i], fh[j]);
#pragma unroll
            for (int i = 0; i < 2; i++)
#pragma unroll
                for (int j = 0; j < 4; j++) mma16816(dd[i][j], al[i], fh[j]);
#pragma unroll
            for (int i = 0; i < 2; i++)
#pragma unroll
                for (int j = 0; j < 4; j++) mma16816(dd[i][j], ah[i], fl[j]);
        }
        __syncthreads();
    }

    // Weighted deterministic scatter (exactly 2 commutative adds per element)
    const int r0 = lane >> 2;
    const int c0 = (lane & 3) * 2;
#pragma unroll
    for (int i = 0; i < 2; i++) {
        const int mA = wm * 32 + i * 16 + r0;
        const int mB = mA + 8;
        const int pidA = s_plist[mA & 127];
        const int pidB = s_plist[mB & 127];
        const float wA = d_wgt[pidA];
        const float wB = d_wgt[pidB];
#pragma unroll
        for (int j = 0; j < 4; j++) {
            const int col = n0 + wn * 32 + j * 8 + c0;
            if (mA < rows) {
                float* p = out + (size_t)(pidA >> 1) * D_MODEL + col;
                atomicAdd(p + 0, wA * dd[i][j][0]);
                atomicAdd(p + 1, wA * dd[i][j][1]);
            }
            if (mB < rows) {
                float* p = out + (size_t)(pidB >> 1) * D_MODEL + col;
                atomicAdd(p + 0, wB * dd[i][j][2]);
                atomicAdd(p + 1, wB * dd[i][j][3]);
            }
        }
    }
}

// ---------------------------------------------------------------------------
// Launch
// ---------------------------------------------------------------------------
extern "C" void kernel_launch(void* const* d_in, const int* in_sizes, int n_in,
                              void* d_out, int out_size) {
    const float* x  = (const float*)d_in[0];
    const float* gw = (const float*)d_in[1];
    const float* wg = (const float*)d_in[2];
    const float* wu = (const float*)d_in[3];
    const float* wd = (const float*)d_in[4];
    float* out = (float*)d_out;

    cudaFuncSetAttribute(gemm1_kernel, cudaFuncAttributeMaxDynamicSharedMemorySize, G1_SMEM);
    cudaFuncSetAttribute(gemm2_kernel, cudaFuncAttributeMaxDynamicSharedMemorySize, G2_SMEM);

    __nv_bfloat16 *xh, *xl, *wgh, *wgl, *wuh, *wul, *wdh, *wdl;
    cudaGetSymbolAddress((void**)&xh, d_x_h);   cudaGetSymbolAddress((void**)&xl, d_x_l);
    cudaGetSymbolAddress((void**)&wgh, d_wg_h); cudaGetSymbolAddress((void**)&wgl, d_wg_l);
    cudaGetSymbolAddress((void**)&wuh, d_wu_h); cudaGetSymbolAddress((void**)&wul, d_wu_l);
    cudaGetSymbolAddress((void**)&wdh, d_wd_h); cudaGetSymbolAddress((void**)&wdl, d_wd_l);

    const int N4 = NTOK * D_MODEL / 4;
    const int W4 = NE * D_FF * D_MODEL / 4;

    init_kernel<<<2048, 256>>>(out);
    conv_kernel<<<1184, 256>>>(x,  xh,  xl,  N4);
    conv_kernel<<<1184, 256>>>(wg, wgh, wgl, W4);
    conv_kernel<<<1184, 256>>>(wu, wuh, wul, W4);
    conv_kernel<<<1184, 256>>>(wd, wdh, wdl, W4);
    router_kernel<<<NTOK / 8, 256>>>(x, gw);
    aux_kernel<<<1, 256>>>(out);
    gemm1_kernel<<<dim3(64, 8, 8), 512, G1_SMEM>>>();
    gemm2_kernel<<<dim3(64, 8, 8), 512, G2_SMEM>>>(out);
}

// round 5
// speedup vs baseline: 2.6893x; 1.1111x over previous
#include <cuda_runtime.h>
#include <cuda_bf16.h>
#include <math.h>
#include <stdint.h>

#define D_MODEL 1024
#define D_FF    1024
#define NE      8
#define NTOK    8192
#define NPAIRS  16384
#define BM      128
#define BN      128
#define BK      32
#define STAGES  3
#define NKT     32

// ---------------------------------------------------------------------------
// Static scratch
// ---------------------------------------------------------------------------
__device__ __nv_bfloat16 d_x_h[(size_t)NTOK * D_MODEL];
__device__ __nv_bfloat16 d_x_l[(size_t)NTOK * D_MODEL];
__device__ __nv_bfloat16 d_wg_h[(size_t)NE * D_FF * D_MODEL];
__device__ __nv_bfloat16 d_wg_l[(size_t)NE * D_FF * D_MODEL];
__device__ __nv_bfloat16 d_wu_h[(size_t)NE * D_FF * D_MODEL];
__device__ __nv_bfloat16 d_wu_l[(size_t)NE * D_FF * D_MODEL];
__device__ __nv_bfloat16 d_wd_h[(size_t)NE * D_MODEL * D_FF];
__device__ __nv_bfloat16 d_wd_l[(size_t)NE * D_MODEL * D_FF];
__device__ __nv_bfloat16 d_act_h[(size_t)NPAIRS * D_FF];
__device__ __nv_bfloat16 d_act_l[(size_t)NPAIRS * D_FF];
__device__ int   d_list[NE * NTOK];
__device__ int   d_cnt[NE];
__device__ float d_wgt[NPAIRS];
__device__ float d_probs[NTOK * NE];

// ---------------------------------------------------------------------------
// Helpers (generic PTX only — compiles on compute_103 family target)
// ---------------------------------------------------------------------------
__device__ __forceinline__ uint32_t smem_u32(const void* p) {
    uint32_t a;
    asm("{ .reg .u64 t; cvta.to.shared.u64 t, %1; cvt.u32.u64 %0, t; }" : "=r"(a) : "l"(p));
    return a;
}
__device__ __forceinline__ void cp16(uint32_t dst, const void* src) {
    asm volatile("cp.async.cg.shared.global [%0], [%1], 16;" :: "r"(dst), "l"(src));
}
#define CP_COMMIT() asm volatile("cp.async.commit_group;" ::: "memory")
#define CP_WAIT1()  asm volatile("cp.async.wait_group 1;" ::: "memory")

// Conflict-free swizzle for 64B rows of 16B chunks:
// phase(row, ch) = (4*row + (ch ^ ((row>>1)&3))) mod 8 — distinct over any
// 8-row ldmatrix read (even rows cover {0..3}, odd rows {4..7} bijectively).
#define SWZ(r, c) ((uint32_t)((r) * 64 + (((c) ^ (((r) >> 1) & 3)) << 4)))

__device__ __forceinline__ void ldmA(uint32_t r[4], uint32_t addr) {
    asm volatile("ldmatrix.sync.aligned.m8n8.x4.shared.b16 {%0,%1,%2,%3}, [%4];"
                 : "=r"(r[0]), "=r"(r[1]), "=r"(r[2]), "=r"(r[3]) : "r"(addr));
}
__device__ __forceinline__ void ldmB(uint32_t r[2], uint32_t addr) {
    asm volatile("ldmatrix.sync.aligned.m8n8.x2.shared.b16 {%0,%1}, [%2];"
                 : "=r"(r[0]), "=r"(r[1]) : "r"(addr));
}
__device__ __forceinline__ void mma16816(float d[4], const uint32_t a[4], const uint32_t b[2]) {
    asm volatile("mma.sync.aligned.m16n8k16.row.col.f32.bf16.bf16.f32 "
                 "{%0,%1,%2,%3}, {%4,%5,%6,%7}, {%8,%9}, {%0,%1,%2,%3};"
                 : "+f"(d[0]), "+f"(d[1]), "+f"(d[2]), "+f"(d[3])
                 : "r"(a[0]), "r"(a[1]), "r"(a[2]), "r"(a[3]), "r"(b[0]), "r"(b[1]));
}
__device__ __forceinline__ uint32_t pack_bf(__nv_bfloat16 a, __nv_bfloat16 b) {
    return (uint32_t)__bfloat16_as_ushort(a) | ((uint32_t)__bfloat16_as_ushort(b) << 16);
}
__device__ __forceinline__ float silu_mul(float g, float u) {
    return (g / (1.f + __expf(-g))) * u;
}

// ---------------------------------------------------------------------------
// Init: zero counters + output region (harness poisons d_out)
// ---------------------------------------------------------------------------
__global__ void init_kernel(float* __restrict__ out) {
    int idx = blockIdx.x * blockDim.x + threadIdx.x;
    if (idx < NE) d_cnt[idx] = 0;
    float4 z = make_float4(0.f, 0.f, 0.f, 0.f);
    float4* o4 = (float4*)out;
    const int n4 = NTOK * D_MODEL / 4;
    for (int i = idx; i < n4; i += gridDim.x * blockDim.x) o4[i] = z;
}

// ---------------------------------------------------------------------------
// Fused hi/lo conversion: x, wg, wu, wd — each exactly 2^21 float4s.
// ---------------------------------------------------------------------------
struct ConvArgs {
    const float* src[4];
    __nv_bfloat16* hi[4];
    __nv_bfloat16* lo[4];
};

__global__ void conv4_kernel(ConvArgs a) {
    const int total = 4 << 21;
    for (int i = blockIdx.x * blockDim.x + threadIdx.x; i < total; i += gridDim.x * blockDim.x) {
        const int reg = i >> 21;
        const int off = i & ((1 << 21) - 1);
        float4 v = ((const float4*)a.src[reg])[off];
        uint32_t* h2 = (uint32_t*)a.hi[reg];
        uint32_t* l2 = (uint32_t*)a.lo[reg];
        __nv_bfloat16 hx = __float2bfloat16(v.x), hy = __float2bfloat16(v.y);
        __nv_bfloat16 hz = __float2bfloat16(v.z), hw = __float2bfloat16(v.w);
        h2[2 * off + 0] = pack_bf(hx, hy);
        h2[2 * off + 1] = pack_bf(hz, hw);
        l2[2 * off + 0] = pack_bf(__float2bfloat16(v.x - __bfloat162float(hx)),
                                  __float2bfloat16(v.y - __bfloat162float(hy)));
        l2[2 * off + 1] = pack_bf(__float2bfloat16(v.z - __bfloat162float(hz)),
                                  __float2bfloat16(v.w - __bfloat162float(hw)));
    }
}

// ---------------------------------------------------------------------------
// Router + aux (verbatim — passed since R1)
// ---------------------------------------------------------------------------
__global__ void router_kernel(const float* __restrict__ x, const float* __restrict__ gw) {
    const int lane = threadIdx.x & 31;
    const int warp = threadIdx.x >> 5;
    const int t = blockIdx.x * (blockDim.x >> 5) + warp;
    if (t >= NTOK) return;

    const float4* xp = (const float4*)(x + (size_t)t * D_MODEL);
    float4 xv[8];
#pragma unroll
    for (int i = 0; i < 8; i++) xv[i] = xp[i * 32 + lane];

    float logit[NE];
#pragma unroll
    for (int e = 0; e < NE; e++) {
        const float4* gp = (const float4*)(gw + e * D_MODEL);
        float s = 0.f;
#pragma unroll
        for (int i = 0; i < 8; i++) {
            float4 g = gp[i * 32 + lane];
            s += xv[i].x * g.x + xv[i].y * g.y + xv[i].z * g.z + xv[i].w * g.w;
        }
#pragma unroll
        for (int o = 16; o > 0; o >>= 1) s += __shfl_xor_sync(0xffffffffu, s, o);
        logit[e] = s;
    }

    if (lane == 0) {
        float m = logit[0];
#pragma unroll
        for (int e = 1; e < NE; e++) m = fmaxf(m, logit[e]);
        float p[NE], sum = 0.f;
#pragma unroll
        for (int e = 0; e < NE; e++) { p[e] = expf(logit[e] - m); sum += p[e]; }
        const float inv = 1.f / sum;
#pragma unroll
        for (int e = 0; e < NE; e++) { p[e] *= inv; d_probs[t * NE + e] = p[e]; }

        int i0 = 0;
#pragma unroll
        for (int e = 1; e < NE; e++) if (p[e] > p[i0]) i0 = e;
        int i1 = (i0 == 0) ? 1 : 0;
#pragma unroll
        for (int e = 0; e < NE; e++) if (e != i0 && p[e] > p[i1]) i1 = e;

        const float s2 = p[i0] + p[i1];
        int pos0 = atomicAdd(&d_cnt[i0], 1);
        d_list[i0 * NTOK + pos0] = 2 * t;
        d_wgt[2 * t] = p[i0] / s2;
        int pos1 = atomicAdd(&d_cnt[i1], 1);
        d_list[i1 * NTOK + pos1] = 2 * t + 1;
        d_wgt[2 * t + 1] = p[i1] / s2;
    }
}

__global__ void aux_kernel(float* __restrict__ out) {
    __shared__ float s[256][NE];
    const int tid = threadIdx.x;
    float acc[NE];
#pragma unroll
    for (int e = 0; e < NE; e++) acc[e] = 0.f;
    for (int t = tid; t < NTOK; t += 256)
#pragma unroll
        for (int e = 0; e < NE; e++) acc[e] += d_probs[t * NE + e];
#pragma unroll
    for (int e = 0; e < NE; e++) s[tid][e] = acc[e];
    __syncthreads();
    if (tid == 0) {
        float aux = 0.f;
        for (int e = 0; e < NE; e++) {
            float ps = 0.f;
            for (int i = 0; i < 256; i++) ps += s[i][e];
            aux += ((float)d_cnt[e] * (1.f / (float)NPAIRS)) * (ps * (1.f / (float)NTOK));
        }
        out[(size_t)NTOK * D_MODEL] = (float)NE * aux;
    }
    if (tid < NE) out[(size_t)NTOK * D_MODEL + 1 + tid] = (float)d_cnt[tid];
}

// ---------------------------------------------------------------------------
// GEMM1 fused: g = x@wg^T, u = x@wu^T (3-term bf16 each), act = silu(g)*u.
// 512 threads (16 warps, 4x4 warp grid, warp tile 32x32 per matrix).
// ---------------------------------------------------------------------------
#define G1_STG  49152
#define G1_SMEM (1024 + STAGES * G1_STG)

__device__ __forceinline__ void g1_issue(int tid, const int* plist,
                                         const __nv_bfloat16* xh, const __nv_bfloat16* xl,
                                         const __nv_bfloat16* gh, const __nv_bfloat16* gl,
                                         const __nv_bfloat16* uh, const __nv_bfloat16* ul,
                                         int n0, int kt, uint32_t base) {
    const int r = tid >> 2, c = tid & 3;
    const uint32_t sw = SWZ(r, c);
    const size_t aoff = (size_t)(plist[r] >> 1) * (D_MODEL * 2) + kt * 64 + c * 16;
    const size_t boff = (size_t)(n0 + r) * (D_MODEL * 2) + kt * 64 + c * 16;
    cp16(base + sw,         (const char*)xh + aoff);
    cp16(base + 8192 + sw,  (const char*)xl + aoff);
    cp16(base + 16384 + sw, (const char*)gh + boff);
    cp16(base + 24576 + sw, (const char*)gl + boff);
    cp16(base + 32768 + sw, (const char*)uh + boff);
    cp16(base + 40960 + sw, (const char*)ul + boff);
}

__global__ __launch_bounds__(512, 1) void gemm1_kernel() {
    const int e = blockIdx.z;
    const int cnt = d_cnt[e];
    const int m0 = blockIdx.x * BM;
    if (m0 >= cnt) return;
    const int n0 = blockIdx.y * BN;

    extern __shared__ __align__(128) char smem[];
    const uint32_t sb = smem_u32(smem);
    const int tid = threadIdx.x;
    const int lane = tid & 31;
    const int w = tid >> 5;
    const int wm = w >> 2, wn = w & 3;
    const int rows = min(BM, cnt - m0);

    int* s_plist = (int*)smem;
    if (tid < BM) s_plist[tid] = (tid < rows) ? d_list[e * NTOK + m0 + tid] : 0;
    __syncthreads();

    const __nv_bfloat16* gh = d_wg_h + ((size_t)e << 20);
    const __nv_bfloat16* gl = d_wg_l + ((size_t)e << 20);
    const __nv_bfloat16* uh = d_wu_h + ((size_t)e << 20);
    const __nv_bfloat16* ul = d_wu_l + ((size_t)e << 20);

    g1_issue(tid, s_plist, d_x_h, d_x_l, gh, gl, uh, ul, n0, 0, sb + 1024);
    CP_COMMIT();
    g1_issue(tid, s_plist, d_x_h, d_x_l, gh, gl, uh, ul, n0, 1, sb + 1024 + G1_STG);
    CP_COMMIT();

    float dg[2][4][4], du[2][4][4];
#pragma unroll
    for (int i = 0; i < 2; i++)
#pragma unroll
        for (int j = 0; j < 4; j++)
#pragma unroll
            for (int k = 0; k < 4; k++) { dg[i][j][k] = 0.f; du[i][j][k] = 0.f; }

    for (int kt = 0; kt < NKT; kt++) {
        CP_WAIT1();
        __syncthreads();
        if (kt + 2 < NKT)
            g1_issue(tid, s_plist, d_x_h, d_x_l, gh, gl, uh, ul, n0,
                     kt + 2, sb + 1024 + ((kt + 2) % STAGES) * G1_STG);
        CP_COMMIT();

        const uint32_t st = sb + 1024 + (kt % STAGES) * G1_STG;
#pragma unroll
        for (int ks = 0; ks < 2; ks++) {
            uint32_t ah[2][4], al[2][4];
#pragma unroll
            for (int i = 0; i < 2; i++) {
                const int row = wm * 32 + i * 16 + (lane & 15);
                const int ch = ks * 2 + (lane >> 4);
                const uint32_t off = SWZ(row, ch);
                ldmA(ah[i], st + off);
                ldmA(al[i], st + 8192 + off);
            }
            {
                uint32_t bh[4][2], bl[4][2];
#pragma unroll
                for (int j = 0; j < 4; j++) {
                    const int row = wn * 32 + j * 8 + (lane & 7);
                    const int ch = ks * 2 + ((lane >> 3) & 1);
                    const uint32_t off = SWZ(row, ch);
                    ldmB(bh[j], st + 16384 + off);
                    ldmB(bl[j], st + 24576 + off);
                }
#pragma unroll
                for (int i = 0; i < 2; i++)
#pragma unroll
                    for (int j = 0; j < 4; j++) mma16816(dg[i][j], ah[i], bh[j]);
#pragma unroll
                for (int i = 0; i < 2; i++)
#pragma unroll
                    for (int j = 0; j < 4; j++) mma16816(dg[i][j], al[i], bh[j]);
#pragma unroll
                for (int i = 0; i < 2; i++)
#pragma unroll
                    for (int j = 0; j < 4; j++) mma16816(dg[i][j], ah[i], bl[j]);
            }
            {
                uint32_t bh[4][2], bl[4][2];
#pragma unroll
                for (int j = 0; j < 4; j++) {
                    const int row = wn * 32 + j * 8 + (lane & 7);
                    const int ch = ks * 2 + ((lane >> 3) & 1);
                    const uint32_t off = SWZ(row, ch);
                    ldmB(bh[j], st + 32768 + off);
                    ldmB(bl[j], st + 40960 + off);
                }
#pragma unroll
                for (int i = 0; i < 2; i++)
#pragma unroll
                    for (int j = 0; j < 4; j++) mma16816(du[i][j], ah[i], bh[j]);
#pragma unroll
                for (int i = 0; i < 2; i++)
#pragma unroll
                    for (int j = 0; j < 4; j++) mma16816(du[i][j], al[i], bh[j]);
#pragma unroll
                for (int i = 0; i < 2; i++)
#pragma unroll
                    for (int j = 0; j < 4; j++) mma16816(du[i][j], ah[i], bl[j]);
            }
        }
        __syncthreads();
    }

    // Epilogue: act = silu(g)*u -> bf16 hi/lo, gathered row scatter
    const int r0 = lane >> 2;
    const int c0 = (lane & 3) * 2;
#pragma unroll
    for (int i = 0; i < 2; i++) {
        const int mA = wm * 32 + i * 16 + r0;
        const int mB = mA + 8;
        const int pidA = s_plist[mA & 127];
        const int pidB = s_plist[mB & 127];
#pragma unroll
        for (int j = 0; j < 4; j++) {
            const int col = n0 + wn * 32 + j * 8 + c0;
            if (mA < rows) {
                const float a0 = silu_mul(dg[i][j][0], du[i][j][0]);
                const float a1 = silu_mul(dg[i][j][1], du[i][j][1]);
                const __nv_bfloat16 h0 = __float2bfloat16(a0);
                const __nv_bfloat16 h1 = __float2bfloat16(a1);
                *(uint32_t*)(d_act_h + (size_t)pidA * D_FF + col) = pack_bf(h0, h1);
                *(uint32_t*)(d_act_l + (size_t)pidA * D_FF + col) =
                    pack_bf(__float2bfloat16(a0 - __bfloat162float(h0)),
                            __float2bfloat16(a1 - __bfloat162float(h1)));
            }
            if (mB < rows) {
                const float a0 = silu_mul(dg[i][j][2], du[i][j][2]);
                const float a1 = silu_mul(dg[i][j][3], du[i][j][3]);
                const __nv_bfloat16 h0 = __float2bfloat16(a0);
                const __nv_bfloat16 h1 = __float2bfloat16(a1);
                *(uint32_t*)(d_act_h + (size_t)pidB * D_FF + col) = pack_bf(h0, h1);
                *(uint32_t*)(d_act_l + (size_t)pidB * D_FF + col) =
                    pack_bf(__float2bfloat16(a0 - __bfloat162float(h0)),
                            __float2bfloat16(a1 - __bfloat162float(h1)));
            }
        }
    }
}

// ---------------------------------------------------------------------------
// GEMM2: eo = act @ wd^T (3-term), weighted atomicAdd scatter into out.
// ---------------------------------------------------------------------------
#define G2_STG  32768
#define G2_SMEM (1024 + STAGES * G2_STG)

__device__ __forceinline__ void g2_issue(int tid, const int* plist,
                                         const __nv_bfloat16* bh, const __nv_bfloat16* bl,
                                         int n0, int kt, uint32_t base) {
    const int r = tid >> 2, c = tid & 3;
    const uint32_t sw = SWZ(r, c);
    const size_t aoff = (size_t)plist[r] * (D_FF * 2) + kt * 64 + c * 16;
    const size_t boff = (size_t)(n0 + r) * (D_FF * 2) + kt * 64 + c * 16;
    cp16(base + sw,         (const char*)d_act_h + aoff);
    cp16(base + 8192 + sw,  (const char*)d_act_l + aoff);
    cp16(base + 16384 + sw, (const char*)bh + boff);
    cp16(base + 24576 + sw, (const char*)bl + boff);
}

__global__ __launch_bounds__(512, 1) void gemm2_kernel(float* __restrict__ out) {
    const int e = blockIdx.z;
    const int cnt = d_cnt[e];
    const int m0 = blockIdx.x * BM;
    if (m0 >= cnt) return;
    const int n0 = blockIdx.y * BN;

    extern __shared__ __align__(128) char smem[];
    const uint32_t sb = smem_u32(smem);
    const int tid = threadIdx.x;
    const int lane = tid & 31;
    const int w = tid >> 5;
    const int wm = w >> 2, wn = w & 3;
    const int rows = min(BM, cnt - m0);

    int* s_plist = (int*)smem;
    if (tid < BM) s_plist[tid] = (tid < rows) ? d_list[e * NTOK + m0 + tid] : 0;
    __syncthreads();

    const __nv_bfloat16* bh = d_wd_h + ((size_t)e << 20);
    const __nv_bfloat16* bl = d_wd_l + ((size_t)e << 20);

    g2_issue(tid, s_plist, bh, bl, n0, 0, sb + 1024);
    CP_COMMIT();
    g2_issue(tid, s_plist, bh, bl, n0, 1, sb + 1024 + G2_STG);
    CP_COMMIT();

    float dd[2][4][4];
#pragma unroll
    for (int i = 0; i < 2; i++)
#pragma unroll
        for (int j = 0; j < 4; j++)
#pragma unroll
            for (int k = 0; k < 4; k++) dd[i][j][k] = 0.f;

    for (int kt = 0; kt < NKT; kt++) {
        CP_WAIT1();
        __syncthreads();
        if (kt + 2 < NKT)
            g2_issue(tid, s_plist, bh, bl, n0, kt + 2,
                     sb + 1024 + ((kt + 2) % STAGES) * G2_STG);
        CP_COMMIT();

        const uint32_t st = sb + 1024 + (kt % STAGES) * G2_STG;
#pragma unroll
        for (int ks = 0; ks < 2; ks++) {
            uint32_t ah[2][4], al[2][4], fh[4][2], fl[4][2];
#pragma unroll
            for (int i = 0; i < 2; i++) {
                const int row = wm * 32 + i * 16 + (lane & 15);
                const int ch = ks * 2 + (lane >> 4);
                const uint32_t off = SWZ(row, ch);
                ldmA(ah[i], st + off);
                ldmA(al[i], st + 8192 + off);
            }
#pragma unroll
            for (int j = 0; j < 4; j++) {
                const int row = wn * 32 + j * 8 + (lane & 7);
                const int ch = ks * 2 + ((lane >> 3) & 1);
                const uint32_t off = SWZ(row, ch);
                ldmB(fh[j], st + 16384 + off);
                ldmB(fl[j], st + 24576 + off);
            }
#pragma unroll
            for (int i = 0; i < 2; i++)
#pragma unroll
                for (int j = 0; j < 4; j++) mma16816(dd[i][j], ah[i], fh[j]);
#pragma unroll
            for (int i = 0; i < 2; i++)
#pragma unroll
                for (int j = 0; j < 4; j++) mma16816(dd[i][j], al[i], fh[j]);
#pragma unroll
            for (int i = 0; i < 2; i++)
#pragma unroll
                for (int j = 0; j < 4; j++) mma16816(dd[i][j], ah[i], fl[j]);
        }
        __syncthreads();
    }

    // Weighted deterministic scatter (exactly 2 commutative adds per element)
    const int r0 = lane >> 2;
    const int c0 = (lane & 3) * 2;
#pragma unroll
    for (int i = 0; i < 2; i++) {
        const int mA = wm * 32 + i * 16 + r0;
        const int mB = mA + 8;
        const int pidA = s_plist[mA & 127];
        const int pidB = s_plist[mB & 127];
        const float wA = d_wgt[pidA];
        const float wB = d_wgt[pidB];
#pragma unroll
        for (int j = 0; j < 4; j++) {
            const int col = n0 + wn * 32 + j * 8 + c0;
            if (mA < rows) {
                float* p = out + (size_t)(pidA >> 1) * D_MODEL + col;
                atomicAdd(p + 0, wA * dd[i][j][0]);
                atomicAdd(p + 1, wA * dd[i][j][1]);
            }
            if (mB < rows) {
                float* p = out + (size_t)(pidB >> 1) * D_MODEL + col;
                atomicAdd(p + 0, wB * dd[i][j][2]);
                atomicAdd(p + 1, wB * dd[i][j][3]);
            }
        }
    }
}

// ---------------------------------------------------------------------------
// Launch
// ---------------------------------------------------------------------------
extern "C" void kernel_launch(void* const* d_in, const int* in_sizes, int n_in,
                              void* d_out, int out_size) {
    const float* x  = (const float*)d_in[0];
    const float* gw = (const float*)d_in[1];
    const float* wg = (const float*)d_in[2];
    const float* wu = (const float*)d_in[3];
    const float* wd = (const float*)d_in[4];
    float* out = (float*)d_out;

    cudaFuncSetAttribute(gemm1_kernel, cudaFuncAttributeMaxDynamicSharedMemorySize, G1_SMEM);
    cudaFuncSetAttribute(gemm2_kernel, cudaFuncAttributeMaxDynamicSharedMemorySize, G2_SMEM);

    ConvArgs ca;
    ca.src[0] = x;  ca.src[1] = wg; ca.src[2] = wu; ca.src[3] = wd;
    cudaGetSymbolAddress((void**)&ca.hi[0], d_x_h);  cudaGetSymbolAddress((void**)&ca.lo[0], d_x_l);
    cudaGetSymbolAddress((void**)&ca.hi[1], d_wg_h); cudaGetSymbolAddress((void**)&ca.lo[1], d_wg_l);
    cudaGetSymbolAddress((void**)&ca.hi[2], d_wu_h); cudaGetSymbolAddress((void**)&ca.lo[2], d_wu_l);
    cudaGetSymbolAddress((void**)&ca.hi[3], d_wd_h); cudaGetSymbolAddress((void**)&ca.lo[3], d_wd_l);

    init_kernel<<<2048, 256>>>(out);
    conv4_kernel<<<4736, 256>>>(ca);
    router_kernel<<<NTOK / 8, 256>>>(x, gw);
    aux_kernel<<<1, 256>>>(out);
    gemm1_kernel<<<dim3(64, 8, 8), 512, G1_SMEM>>>();
    gemm2_kernel<<<dim3(64, 8, 8), 512, G2_SMEM>>>(out);
}

// round 6
// speedup vs baseline: 2.8661x; 1.0657x over previous
#include <cuda_runtime.h>
#include <cuda_bf16.h>
#include <math.h>
#include <stdint.h>

#define D_MODEL 1024
#define D_FF    1024
#define NE      8
#define NTOK    8192
#define NPAIRS  16384
#define BM      128
#define BN      128
#define NKT     32

// ---------------------------------------------------------------------------
// Static scratch
// ---------------------------------------------------------------------------
__device__ __nv_bfloat16 d_x_h[(size_t)NTOK * D_MODEL];
__device__ __nv_bfloat16 d_x_l[(size_t)NTOK * D_MODEL];
__device__ __nv_bfloat16 d_wg_h[(size_t)NE * D_FF * D_MODEL];
__device__ __nv_bfloat16 d_wg_l[(size_t)NE * D_FF * D_MODEL];
__device__ __nv_bfloat16 d_wu_h[(size_t)NE * D_FF * D_MODEL];
__device__ __nv_bfloat16 d_wu_l[(size_t)NE * D_FF * D_MODEL];
__device__ __nv_bfloat16 d_wd_h[(size_t)NE * D_MODEL * D_FF];
__device__ __nv_bfloat16 d_wd_l[(size_t)NE * D_MODEL * D_FF];
__device__ __nv_bfloat16 d_act_h[(size_t)NPAIRS * D_FF];
__device__ __nv_bfloat16 d_act_l[(size_t)NPAIRS * D_FF];
__device__ int   d_list[NE * NTOK];
__device__ int   d_cnt[NE];
__device__ float d_wgt[NPAIRS];
__device__ float d_probs[NTOK * NE];

// ---------------------------------------------------------------------------
// Helpers (generic PTX only)
// ---------------------------------------------------------------------------
__device__ __forceinline__ uint32_t smem_u32(const void* p) {
    uint32_t a;
    asm("{ .reg .u64 t; cvta.to.shared.u64 t, %1; cvt.u32.u64 %0, t; }" : "=r"(a) : "l"(p));
    return a;
}
__device__ __forceinline__ void cp16(uint32_t dst, const void* src) {
    asm volatile("cp.async.cg.shared.global [%0], [%1], 16;" :: "r"(dst), "l"(src));
}
#define CP_COMMIT() asm volatile("cp.async.commit_group;" ::: "memory")
#define CP_WAIT1()  asm volatile("cp.async.wait_group 1;" ::: "memory")
#define CP_WAIT2()  asm volatile("cp.async.wait_group 2;" ::: "memory")

// Conflict-free swizzle for 64B rows of 16B chunks.
#define SWZ(r, c) ((uint32_t)((r) * 64 + (((c) ^ (((r) >> 1) & 3)) << 4)))

__device__ __forceinline__ void ldmA(uint32_t r[4], uint32_t addr) {
    asm volatile("ldmatrix.sync.aligned.m8n8.x4.shared.b16 {%0,%1,%2,%3}, [%4];"
                 : "=r"(r[0]), "=r"(r[1]), "=r"(r[2]), "=r"(r[3]) : "r"(addr));
}
__device__ __forceinline__ void ldmB(uint32_t r[2], uint32_t addr) {
    asm volatile("ldmatrix.sync.aligned.m8n8.x2.shared.b16 {%0,%1}, [%2];"
                 : "=r"(r[0]), "=r"(r[1]) : "r"(addr));
}
__device__ __forceinline__ void mma16816(float d[4], const uint32_t a[4], const uint32_t b[2]) {
    asm volatile("mma.sync.aligned.m16n8k16.row.col.f32.bf16.bf16.f32 "
                 "{%0,%1,%2,%3}, {%4,%5,%6,%7}, {%8,%9}, {%0,%1,%2,%3};"
                 : "+f"(d[0]), "+f"(d[1]), "+f"(d[2]), "+f"(d[3])
                 : "r"(a[0]), "r"(a[1]), "r"(a[2]), "r"(a[3]), "r"(b[0]), "r"(b[1]));
}
__device__ __forceinline__ uint32_t pack_bf(__nv_bfloat16 a, __nv_bfloat16 b) {
    return (uint32_t)__bfloat16_as_ushort(a) | ((uint32_t)__bfloat16_as_ushort(b) << 16);
}
__device__ __forceinline__ float silu_mul(float g, float u) {
    return (g / (1.f + __expf(-g))) * u;
}

// ---------------------------------------------------------------------------
// Init: zero counters + output region
// ---------------------------------------------------------------------------
__global__ void init_kernel(float* __restrict__ out) {
    int idx = blockIdx.x * blockDim.x + threadIdx.x;
    if (idx < NE) d_cnt[idx] = 0;
    float4 z = make_float4(0.f, 0.f, 0.f, 0.f);
    float4* o4 = (float4*)out;
    const int n4 = NTOK * D_MODEL / 4;
    for (int i = idx; i < n4; i += gridDim.x * blockDim.x) o4[i] = z;
}

// ---------------------------------------------------------------------------
// Fused hi/lo conversion: 4 regions of exactly 2^21 float4s
// ---------------------------------------------------------------------------
struct ConvArgs {
    const float* src[4];
    __nv_bfloat16* hi[4];
    __nv_bfloat16* lo[4];
};

__global__ void conv4_kernel(ConvArgs a) {
    const int total = 4 << 21;
    for (int i = blockIdx.x * blockDim.x + threadIdx.x; i < total; i += gridDim.x * blockDim.x) {
        const int reg = i >> 21;
        const int off = i & ((1 << 21) - 1);
        float4 v = ((const float4*)a.src[reg])[off];
        uint32_t* h2 = (uint32_t*)a.hi[reg];
        uint32_t* l2 = (uint32_t*)a.lo[reg];
        __nv_bfloat16 hx = __float2bfloat16(v.x), hy = __float2bfloat16(v.y);
        __nv_bfloat16 hz = __float2bfloat16(v.z), hw = __float2bfloat16(v.w);
        h2[2 * off + 0] = pack_bf(hx, hy);
        h2[2 * off + 1] = pack_bf(hz, hw);
        l2[2 * off + 0] = pack_bf(__float2bfloat16(v.x - __bfloat162float(hx)),
                                  __float2bfloat16(v.y - __bfloat162float(hy)));
        l2[2 * off + 1] = pack_bf(__float2bfloat16(v.z - __bfloat162float(hz)),
                                  __float2bfloat16(v.w - __bfloat162float(hw)));
    }
}

// ---------------------------------------------------------------------------
// Router (verbatim — passed since R1)
// ---------------------------------------------------------------------------
__global__ void router_kernel(const float* __restrict__ x, const float* __restrict__ gw) {
    const int lane = threadIdx.x & 31;
    const int warp = threadIdx.x >> 5;
    const int t = blockIdx.x * (blockDim.x >> 5) + warp;
    if (t >= NTOK) return;

    const float4* xp = (const float4*)(x + (size_t)t * D_MODEL);
    float4 xv[8];
#pragma unroll
    for (int i = 0; i < 8; i++) xv[i] = xp[i * 32 + lane];

    float logit[NE];
#pragma unroll
    for (int e = 0; e < NE; e++) {
        const float4* gp = (const float4*)(gw + e * D_MODEL);
        float s = 0.f;
#pragma unroll
        for (int i = 0; i < 8; i++) {
            float4 g = gp[i * 32 + lane];
            s += xv[i].x * g.x + xv[i].y * g.y + xv[i].z * g.z + xv[i].w * g.w;
        }
#pragma unroll
        for (int o = 16; o > 0; o >>= 1) s += __shfl_xor_sync(0xffffffffu, s, o);
        logit[e] = s;
    }

    if (lane == 0) {
        float m = logit[0];
#pragma unroll
        for (int e = 1; e < NE; e++) m = fmaxf(m, logit[e]);
        float p[NE], sum = 0.f;
#pragma unroll
        for (int e = 0; e < NE; e++) { p[e] = expf(logit[e] - m); sum += p[e]; }
        const float inv = 1.f / sum;
#pragma unroll
        for (int e = 0; e < NE; e++) { p[e] *= inv; d_probs[t * NE + e] = p[e]; }

        int i0 = 0;
#pragma unroll
        for (int e = 1; e < NE; e++) if (p[e] > p[i0]) i0 = e;
        int i1 = (i0 == 0) ? 1 : 0;
#pragma unroll
        for (int e = 0; e < NE; e++) if (e != i0 && p[e] > p[i1]) i1 = e;

        const float s2 = p[i0] + p[i1];
        int pos0 = atomicAdd(&d_cnt[i0], 1);
        d_list[i0 * NTOK + pos0] = 2 * t;
        d_wgt[2 * t] = p[i0] / s2;
        int pos1 = atomicAdd(&d_cnt[i1], 1);
        d_list[i1 * NTOK + pos1] = 2 * t + 1;
        d_wgt[2 * t + 1] = p[i1] / s2;
    }
}

// ---------------------------------------------------------------------------
// Aux loss: parallel reduction (was 20 us single-thread serial)
// ---------------------------------------------------------------------------
__global__ void aux_kernel(float* __restrict__ out) {
    __shared__ float s[256][NE];
    __shared__ float ps[NE];
    const int tid = threadIdx.x;
    float acc[NE];
#pragma unroll
    for (int e = 0; e < NE; e++) acc[e] = 0.f;
    for (int t = tid; t < NTOK; t += 256)
#pragma unroll
        for (int e = 0; e < NE; e++) acc[e] += d_probs[t * NE + e];
#pragma unroll
    for (int e = 0; e < NE; e++) s[tid][e] = acc[e];
    __syncthreads();
    const int w = tid >> 5, lane = tid & 31;
    if (w < NE) {
        float v = 0.f;
        for (int i = lane; i < 256; i += 32) v += s[i][w];
#pragma unroll
        for (int o = 16; o > 0; o >>= 1) v += __shfl_xor_sync(0xffffffffu, v, o);
        if (lane == 0) ps[w] = v;
    }
    __syncthreads();
    if (tid == 0) {
        float aux = 0.f;
        for (int e = 0; e < NE; e++)
            aux += ((float)d_cnt[e] * (1.f / (float)NPAIRS)) * (ps[e] * (1.f / (float)NTOK));
        out[(size_t)NTOK * D_MODEL] = (float)NE * aux;
    }
    if (tid < NE) out[(size_t)NTOK * D_MODEL + 1 + tid] = (float)d_cnt[tid];
}

// ---------------------------------------------------------------------------
// GEMM1 fused: 512 threads, 4x4 warp grid, 32x32 warp tiles, 4-stage pipeline
// ---------------------------------------------------------------------------
#define G1_STAGES 4
#define G1_STG  49152
#define G1_SMEM (1024 + G1_STAGES * G1_STG)

__device__ __forceinline__ void g1_issue(int tid, const int* plist,
                                         const __nv_bfloat16* xh, const __nv_bfloat16* xl,
                                         const __nv_bfloat16* gh, const __nv_bfloat16* gl,
                                         const __nv_bfloat16* uh, const __nv_bfloat16* ul,
                                         int n0, int kt, uint32_t base) {
    const int r = tid >> 2, c = tid & 3;
    const uint32_t sw = SWZ(r, c);
    const size_t aoff = (size_t)(plist[r] >> 1) * (D_MODEL * 2) + kt * 64 + c * 16;
    const size_t boff = (size_t)(n0 + r) * (D_MODEL * 2) + kt * 64 + c * 16;
    cp16(base + sw,         (const char*)xh + aoff);
    cp16(base + 8192 + sw,  (const char*)xl + aoff);
    cp16(base + 16384 + sw, (const char*)gh + boff);
    cp16(base + 24576 + sw, (const char*)gl + boff);
    cp16(base + 32768 + sw, (const char*)uh + boff);
    cp16(base + 40960 + sw, (const char*)ul + boff);
}

__global__ __launch_bounds__(512, 1) void gemm1_kernel() {
    const int e = blockIdx.z;
    const int cnt = d_cnt[e];
    const int m0 = blockIdx.x * BM;
    if (m0 >= cnt) return;
    const int n0 = blockIdx.y * BN;

    extern __shared__ __align__(128) char smem[];
    const uint32_t sb = smem_u32(smem);
    const int tid = threadIdx.x;
    const int lane = tid & 31;
    const int w = tid >> 5;
    const int wm = w >> 2, wn = w & 3;
    const int rows = min(BM, cnt - m0);

    int* s_plist = (int*)smem;
    if (tid < BM) s_plist[tid] = (tid < rows) ? d_list[e * NTOK + m0 + tid] : 0;
    __syncthreads();

    const __nv_bfloat16* gh = d_wg_h + ((size_t)e << 20);
    const __nv_bfloat16* gl = d_wg_l + ((size_t)e << 20);
    const __nv_bfloat16* uh = d_wu_h + ((size_t)e << 20);
    const __nv_bfloat16* ul = d_wu_l + ((size_t)e << 20);

    g1_issue(tid, s_plist, d_x_h, d_x_l, gh, gl, uh, ul, n0, 0, sb + 1024);
    CP_COMMIT();
    g1_issue(tid, s_plist, d_x_h, d_x_l, gh, gl, uh, ul, n0, 1, sb + 1024 + G1_STG);
    CP_COMMIT();
    g1_issue(tid, s_plist, d_x_h, d_x_l, gh, gl, uh, ul, n0, 2, sb + 1024 + 2 * G1_STG);
    CP_COMMIT();

    float dg[2][4][4], du[2][4][4];
#pragma unroll
    for (int i = 0; i < 2; i++)
#pragma unroll
        for (int j = 0; j < 4; j++)
#pragma unroll
            for (int k = 0; k < 4; k++) { dg[i][j][k] = 0.f; du[i][j][k] = 0.f; }

    for (int kt = 0; kt < NKT; kt++) {
        CP_WAIT2();
        __syncthreads();
        if (kt + 3 < NKT)
            g1_issue(tid, s_plist, d_x_h, d_x_l, gh, gl, uh, ul, n0,
                     kt + 3, sb + 1024 + ((kt + 3) % G1_STAGES) * G1_STG);
        CP_COMMIT();

        const uint32_t st = sb + 1024 + (kt % G1_STAGES) * G1_STG;
#pragma unroll
        for (int ks = 0; ks < 2; ks++) {
            uint32_t ah[2][4], al[2][4];
#pragma unroll
            for (int i = 0; i < 2; i++) {
                const int row = wm * 32 + i * 16 + (lane & 15);
                const int ch = ks * 2 + (lane >> 4);
                const uint32_t off = SWZ(row, ch);
                ldmA(ah[i], st + off);
                ldmA(al[i], st + 8192 + off);
            }
            {
                uint32_t bh[4][2], bl[4][2];
#pragma unroll
                for (int j = 0; j < 4; j++) {
                    const int row = wn * 32 + j * 8 + (lane & 7);
                    const int ch = ks * 2 + ((lane >> 3) & 1);
                    const uint32_t off = SWZ(row, ch);
                    ldmB(bh[j], st + 16384 + off);
                    ldmB(bl[j], st + 24576 + off);
                }
#pragma unroll
                for (int i = 0; i < 2; i++)
#pragma unroll
                    for (int j = 0; j < 4; j++) mma16816(dg[i][j], ah[i], bh[j]);
#pragma unroll
                for (int i = 0; i < 2; i++)
#pragma unroll
                    for (int j = 0; j < 4; j++) mma16816(dg[i][j], al[i], bh[j]);
#pragma unroll
                for (int i = 0; i < 2; i++)
#pragma unroll
                    for (int j = 0; j < 4; j++) mma16816(dg[i][j], ah[i], bl[j]);
            }
            {
                uint32_t bh[4][2], bl[4][2];
#pragma unroll
                for (int j = 0; j < 4; j++) {
                    const int row = wn * 32 + j * 8 + (lane & 7);
                    const int ch = ks * 2 + ((lane >> 3) & 1);
                    const uint32_t off = SWZ(row, ch);
                    ldmB(bh[j], st + 32768 + off);
                    ldmB(bl[j], st + 40960 + off);
                }
#pragma unroll
                for (int i = 0; i < 2; i++)
#pragma unroll
                    for (int j = 0; j < 4; j++) mma16816(du[i][j], ah[i], bh[j]);
#pragma unroll
                for (int i = 0; i < 2; i++)
#pragma unroll
                    for (int j = 0; j < 4; j++) mma16816(du[i][j], al[i], bh[j]);
#pragma unroll
                for (int i = 0; i < 2; i++)
#pragma unroll
                    for (int j = 0; j < 4; j++) mma16816(du[i][j], ah[i], bl[j]);
            }
        }
        __syncthreads();
    }

    // Epilogue: act = silu(g)*u -> bf16 hi/lo
    const int r0 = lane >> 2;
    const int c0 = (lane & 3) * 2;
#pragma unroll
    for (int i = 0; i < 2; i++) {
        const int mA = wm * 32 + i * 16 + r0;
        const int mB = mA + 8;
        const int pidA = s_plist[mA & 127];
        const int pidB = s_plist[mB & 127];
#pragma unroll
        for (int j = 0; j < 4; j++) {
            const int col = n0 + wn * 32 + j * 8 + c0;
            if (mA < rows) {
                const float a0 = silu_mul(dg[i][j][0], du[i][j][0]);
                const float a1 = silu_mul(dg[i][j][1], du[i][j][1]);
                const __nv_bfloat16 h0 = __float2bfloat16(a0);
                const __nv_bfloat16 h1 = __float2bfloat16(a1);
                *(uint32_t*)(d_act_h + (size_t)pidA * D_FF + col) = pack_bf(h0, h1);
                *(uint32_t*)(d_act_l + (size_t)pidA * D_FF + col) =
                    pack_bf(__float2bfloat16(a0 - __bfloat162float(h0)),
                            __float2bfloat16(a1 - __bfloat162float(h1)));
            }
            if (mB < rows) {
                const float a0 = silu_mul(dg[i][j][2], du[i][j][2]);
                const float a1 = silu_mul(dg[i][j][3], du[i][j][3]);
                const __nv_bfloat16 h0 = __float2bfloat16(a0);
                const __nv_bfloat16 h1 = __float2bfloat16(a1);
                *(uint32_t*)(d_act_h + (size_t)pidB * D_FF + col) = pack_bf(h0, h1);
                *(uint32_t*)(d_act_l + (size_t)pidB * D_FF + col) =
                    pack_bf(__float2bfloat16(a0 - __bfloat162float(h0)),
                            __float2bfloat16(a1 - __bfloat162float(h1)));
            }
        }
    }
}

// ---------------------------------------------------------------------------
// GEMM2: 256 threads, 2x4 warp grid, 64x32 warp tiles, 2 CTAs/SM, float2 atomics
// ---------------------------------------------------------------------------
#define G2_STAGES 3
#define G2_STG  32768
#define G2_SMEM (1024 + G2_STAGES * G2_STG)

__device__ __forceinline__ void g2_issue(int tid, const int* plist,
                                         const __nv_bfloat16* bh, const __nv_bfloat16* bl,
                                         int n0, int kt, uint32_t base) {
#pragma unroll
    for (int q = 0; q < 2; q++) {
        const int id = tid + q * 256;
        const int r = id >> 2, c = id & 3;
        const uint32_t sw = SWZ(r, c);
        const size_t aoff = (size_t)plist[r] * (D_FF * 2) + kt * 64 + c * 16;
        const size_t boff = (size_t)(n0 + r) * (D_FF * 2) + kt * 64 + c * 16;
        cp16(base + sw,         (const char*)d_act_h + aoff);
        cp16(base + 8192 + sw,  (const char*)d_act_l + aoff);
        cp16(base + 16384 + sw, (const char*)bh + boff);
        cp16(base + 24576 + sw, (const char*)bl + boff);
    }
}

__global__ __launch_bounds__(256, 2) void gemm2_kernel(float* __restrict__ out) {
    const int e = blockIdx.z;
    const int cnt = d_cnt[e];
    const int m0 = blockIdx.x * BM;
    if (m0 >= cnt) return;
    const int n0 = blockIdx.y * BN;

    extern __shared__ __align__(128) char smem[];
    const uint32_t sb = smem_u32(smem);
    const int tid = threadIdx.x;
    const int lane = tid & 31;
    const int w = tid >> 5;
    const int wm = w >> 2, wn = w & 3;   // wm 0..1 (64-row slabs), wn 0..3 (32-col)
    const int rows = min(BM, cnt - m0);

    int* s_plist = (int*)smem;
    if (tid < BM) s_plist[tid] = (tid < rows) ? d_list[e * NTOK + m0 + tid] : 0;
    __syncthreads();

    const __nv_bfloat16* bh = d_wd_h + ((size_t)e << 20);
    const __nv_bfloat16* bl = d_wd_l + ((size_t)e << 20);

    g2_issue(tid, s_plist, bh, bl, n0, 0, sb + 1024);
    CP_COMMIT();
    g2_issue(tid, s_plist, bh, bl, n0, 1, sb + 1024 + G2_STG);
    CP_COMMIT();

    float dd[4][4][4];
#pragma unroll
    for (int i = 0; i < 4; i++)
#pragma unroll
        for (int j = 0; j < 4; j++)
#pragma unroll
            for (int k = 0; k < 4; k++) dd[i][j][k] = 0.f;

    for (int kt = 0; kt < NKT; kt++) {
        CP_WAIT1();
        __syncthreads();
        if (kt + 2 < NKT)
            g2_issue(tid, s_plist, bh, bl, n0, kt + 2,
                     sb + 1024 + ((kt + 2) % G2_STAGES) * G2_STG);
        CP_COMMIT();

        const uint32_t st = sb + 1024 + (kt % G2_STAGES) * G2_STG;
#pragma unroll
        for (int ks = 0; ks < 2; ks++) {
            uint32_t ah[4][4], al[4][4];
#pragma unroll
            for (int i = 0; i < 4; i++) {
                const int row = wm * 64 + i * 16 + (lane & 15);
                const int ch = ks * 2 + (lane >> 4);
                const uint32_t off = SWZ(row, ch);
                ldmA(ah[i], st + off);
                ldmA(al[i], st + 8192 + off);
            }
#pragma unroll
            for (int j = 0; j < 4; j++) {
                const int row = wn * 32 + j * 8 + (lane & 7);
                const int ch = ks * 2 + ((lane >> 3) & 1);
                const uint32_t off = SWZ(row, ch);
                uint32_t fh[2], fl[2];
                ldmB(fh, st + 16384 + off);
                ldmB(fl, st + 24576 + off);
#pragma unroll
                for (int i = 0; i < 4; i++) mma16816(dd[i][j], ah[i], fh);
#pragma unroll
                for (int i = 0; i < 4; i++) mma16816(dd[i][j], al[i], fh);
#pragma unroll
                for (int i = 0; i < 4; i++) mma16816(dd[i][j], ah[i], fl);
            }
        }
        __syncthreads();
    }

    // Weighted deterministic scatter: float2 vector atomics (2 adds/element total)
    const int r0 = lane >> 2;
    const int c0 = (lane & 3) * 2;
#pragma unroll
    for (int i = 0; i < 4; i++) {
        const int mA = wm * 64 + i * 16 + r0;
        const int mB = mA + 8;
        const int pidA = s_plist[mA & 127];
        const int pidB = s_plist[mB & 127];
        const float wA = d_wgt[pidA];
        const float wB = d_wgt[pidB];
#pragma unroll
        for (int j = 0; j < 4; j++) {
            const int col = n0 + wn * 32 + j * 8 + c0;
            if (mA < rows) {
                float2* p = (float2*)(out + (size_t)(pidA >> 1) * D_MODEL + col);
                atomicAdd(p, make_float2(wA * dd[i][j][0], wA * dd[i][j][1]));
            }
            if (mB < rows) {
                float2* p = (float2*)(out + (size_t)(pidB >> 1) * D_MODEL + col);
                atomicAdd(p, make_float2(wB * dd[i][j][2], wB * dd[i][j][3]));
            }
        }
    }
}

// ---------------------------------------------------------------------------
// Launch
// ---------------------------------------------------------------------------
extern "C" void kernel_launch(void* const* d_in, const int* in_sizes, int n_in,
                              void* d_out, int out_size) {
    const float* x  = (const float*)d_in[0];
    const float* gw = (const float*)d_in[1];
    const float* wg = (const float*)d_in[2];
    const float* wu = (const float*)d_in[3];
    const float* wd = (const float*)d_in[4];
    float* out = (float*)d_out;

    cudaFuncSetAttribute(gemm1_kernel, cudaFuncAttributeMaxDynamicSharedMemorySize, G1_SMEM);
    cudaFuncSetAttribute(gemm2_kernel, cudaFuncAttributeMaxDynamicSharedMemorySize, G2_SMEM);

    ConvArgs ca;
    ca.src[0] = x;  ca.src[1] = wg; ca.src[2] = wu; ca.src[3] = wd;
    cudaGetSymbolAddress((void**)&ca.hi[0], d_x_h);  cudaGetSymbolAddress((void**)&ca.lo[0], d_x_l);
    cudaGetSymbolAddress((void**)&ca.hi[1], d_wg_h); cudaGetSymbolAddress((void**)&ca.lo[1], d_wg_l);
    cudaGetSymbolAddress((void**)&ca.hi[2], d_wu_h); cudaGetSymbolAddress((void**)&ca.lo[2], d_wu_l);
    cudaGetSymbolAddress((void**)&ca.hi[3], d_wd_h); cudaGetSymbolAddress((void**)&ca.lo[3], d_wd_l);

    init_kernel<<<2048, 256>>>(out);
    conv4_kernel<<<4736, 256>>>(ca);
    router_kernel<<<NTOK / 8, 256>>>(x, gw);
    aux_kernel<<<1, 256>>>(out);
    gemm1_kernel<<<dim3(64, 8, 8), 512, G1_SMEM>>>();
    gemm2_kernel<<<dim3(64, 8, 8), 256, G2_SMEM>>>(out);
}

// round 9
// speedup vs baseline: 4.0283x; 1.4055x over previous
#include <cuda_runtime.h>
#include <cuda_fp16.h>
#include <math.h>
#include <stdint.h>

#define D_MODEL 1024
#define D_FF    1024
#define NE      8
#define NTOK    8192
#define NPAIRS  16384
#define BM      128
#define BN      128
#define NKT     32

// ---------------------------------------------------------------------------
// Static scratch (fp16: A-side tensors split hi/lo, weights single)
// ---------------------------------------------------------------------------
__device__ __half d_x_h[(size_t)NTOK * D_MODEL];
__device__ __half d_x_l[(size_t)NTOK * D_MODEL];
__device__ __half d_wg[(size_t)NE * D_FF * D_MODEL];
__device__ __half d_wu[(size_t)NE * D_FF * D_MODEL];
__device__ __half d_wd[(size_t)NE * D_MODEL * D_FF];
__device__ __half d_act_h[(size_t)NPAIRS * D_FF];
__device__ __half d_act_l[(size_t)NPAIRS * D_FF];
__device__ int   d_list[NE * NTOK];
__device__ int   d_cnt[NE];
__device__ float d_wgt[NPAIRS];
__device__ float d_probs[NTOK * NE];
__device__ float d_auxp[32 * NE];

// ---------------------------------------------------------------------------
// Helpers (generic PTX only)
// ---------------------------------------------------------------------------
__device__ __forceinline__ uint32_t smem_u32(const void* p) {
    uint32_t a;
    asm("{ .reg .u64 t; cvta.to.shared.u64 t, %1; cvt.u32.u64 %0, t; }" : "=r"(a) : "l"(p));
    return a;
}
__device__ __forceinline__ void cp16(uint32_t dst, const void* src) {
    asm volatile("cp.async.cg.shared.global [%0], [%1], 16;" :: "r"(dst), "l"(src));
}
#define CP_COMMIT() asm volatile("cp.async.commit_group;" ::: "memory")
#define CP_WAIT2()  asm volatile("cp.async.wait_group 2;" ::: "memory")

// Conflict-free swizzle for 64B rows of 16B chunks.
#define SWZ(r, c) ((uint32_t)((r) * 64 + (((c) ^ (((r) >> 1) & 3)) << 4)))

__device__ __forceinline__ void ldmA(uint32_t r[4], uint32_t addr) {
    asm volatile("ldmatrix.sync.aligned.m8n8.x4.shared.b16 {%0,%1,%2,%3}, [%4];"
                 : "=r"(r[0]), "=r"(r[1]), "=r"(r[2]), "=r"(r[3]) : "r"(addr));
}
__device__ __forceinline__ void ldmB(uint32_t r[2], uint32_t addr) {
    asm volatile("ldmatrix.sync.aligned.m8n8.x2.shared.b16 {%0,%1}, [%2];"
                 : "=r"(r[0]), "=r"(r[1]) : "r"(addr));
}
__device__ __forceinline__ void mma16816(float d[4], const uint32_t a[4], const uint32_t b[2]) {
    asm volatile("mma.sync.aligned.m16n8k16.row.col.f32.f16.f16.f32 "
                 "{%0,%1,%2,%3}, {%4,%5,%6,%7}, {%8,%9}, {%0,%1,%2,%3};"
                 : "+f"(d[0]), "+f"(d[1]), "+f"(d[2]), "+f"(d[3])
                 : "r"(a[0]), "r"(a[1]), "r"(a[2]), "r"(a[3]), "r"(b[0]), "r"(b[1]));
}
__device__ __forceinline__ uint32_t pack_h(__half a, __half b) {
    return (uint32_t)__half_as_ushort(a) | ((uint32_t)__half_as_ushort(b) << 16);
}
__device__ __forceinline__ float silu_mul(float g, float u) {
    return (g / (1.f + __expf(-g))) * u;
}

// ---------------------------------------------------------------------------
// Init: zero counters + output region
// ---------------------------------------------------------------------------
__global__ void init_kernel(float* __restrict__ out) {
    int idx = blockIdx.x * blockDim.x + threadIdx.x;
    if (idx < NE) d_cnt[idx] = 0;
    float4 z = make_float4(0.f, 0.f, 0.f, 0.f);
    float4* o4 = (float4*)out;
    const int n4 = NTOK * D_MODEL / 4;
    for (int i = idx; i < n4; i += gridDim.x * blockDim.x) o4[i] = z;
}

// ---------------------------------------------------------------------------
// Conversion: region 0 = x (split fp16 hi/lo), regions 1-3 = weights (fp16)
// ---------------------------------------------------------------------------
struct ConvArgs {
    const float* src[4];
    __half* hi[4];
    __half* lo;      // only for region 0
};

__global__ void conv4_kernel(ConvArgs a) {
    const int total = 4 << 21;
    for (int i = blockIdx.x * blockDim.x + threadIdx.x; i < total; i += gridDim.x * blockDim.x) {
        const int reg = i >> 21;
        const int off = i & ((1 << 21) - 1);
        float4 v = ((const float4*)a.src[reg])[off];
        __half hx = __float2half(v.x), hy = __float2half(v.y);
        __half hz = __float2half(v.z), hw = __float2half(v.w);
        uint32_t* h2 = (uint32_t*)a.hi[reg];
        h2[2 * off + 0] = pack_h(hx, hy);
        h2[2 * off + 1] = pack_h(hz, hw);
        if (reg == 0) {
            uint32_t* l2 = (uint32_t*)a.lo;
            l2[2 * off + 0] = pack_h(__float2half(v.x - __half2float(hx)),
                                     __float2half(v.y - __half2float(hy)));
            l2[2 * off + 1] = pack_h(__float2half(v.z - __half2float(hz)),
                                     __float2half(v.w - __half2float(hw)));
        }
    }
}

// ---------------------------------------------------------------------------
// Router (verbatim — passed since R1)
// ---------------------------------------------------------------------------
__global__ void router_kernel(const float* __restrict__ x, const float* __restrict__ gw) {
    const int lane = threadIdx.x & 31;
    const int warp = threadIdx.x >> 5;
    const int t = blockIdx.x * (blockDim.x >> 5) + warp;
    if (t >= NTOK) return;

    const float4* xp = (const float4*)(x + (size_t)t * D_MODEL);
    float4 xv[8];
#pragma unroll
    for (int i = 0; i < 8; i++) xv[i] = xp[i * 32 + lane];

    float logit[NE];
#pragma unroll
    for (int e = 0; e < NE; e++) {
        const float4* gp = (const float4*)(gw + e * D_MODEL);
        float s = 0.f;
#pragma unroll
        for (int i = 0; i < 8; i++) {
            float4 g = gp[i * 32 + lane];
            s += xv[i].x * g.x + xv[i].y * g.y + xv[i].z * g.z + xv[i].w * g.w;
        }
#pragma unroll
        for (int o = 16; o > 0; o >>= 1) s += __shfl_xor_sync(0xffffffffu, s, o);
        logit[e] = s;
    }

    if (lane == 0) {
        float m = logit[0];
#pragma unroll
        for (int e = 1; e < NE; e++) m = fmaxf(m, logit[e]);
        float p[NE], sum = 0.f;
#pragma unroll
        for (int e = 0; e < NE; e++) { p[e] = expf(logit[e] - m); sum += p[e]; }
        const float inv = 1.f / sum;
#pragma unroll
        for (int e = 0; e < NE; e++) { p[e] *= inv; d_probs[t * NE + e] = p[e]; }

        int i0 = 0;
#pragma unroll
        for (int e = 1; e < NE; e++) if (p[e] > p[i0]) i0 = e;
        int i1 = (i0 == 0) ? 1 : 0;
#pragma unroll
        for (int e = 0; e < NE; e++) if (e != i0 && p[e] > p[i1]) i1 = e;

        const float s2 = p[i0] + p[i1];
        int pos0 = atomicAdd(&d_cnt[i0], 1);
        d_list[i0 * NTOK + pos0] = 2 * t;
        d_wgt[2 * t] = p[i0] / s2;
        int pos1 = atomicAdd(&d_cnt[i1], 1);
        d_list[i1 * NTOK + pos1] = 2 * t + 1;
        d_wgt[2 * t + 1] = p[i1] / s2;
    }
}

// ---------------------------------------------------------------------------
// Aux loss: 32-block partials + tiny finalize (fixed-order, deterministic)
// ---------------------------------------------------------------------------
__global__ void aux_part_kernel() {
    __shared__ float s[256][NE];
    const int tid = threadIdx.x;
    const int t = blockIdx.x * 256 + tid;
#pragma unroll
    for (int e = 0; e < NE; e++) s[tid][e] = d_probs[t * NE + e];
    __syncthreads();
    const int w = tid >> 5, lane = tid & 31;
    if (w < NE) {
        float v = 0.f;
        for (int i = lane; i < 256; i += 32) v += s[i][w];
#pragma unroll
        for (int o = 16; o > 0; o >>= 1) v += __shfl_xor_sync(0xffffffffu, v, o);
        if (lane == 0) d_auxp[blockIdx.x * NE + w] = v;
    }
}

__global__ void aux_fin_kernel(float* __restrict__ out) {
    const int tid = threadIdx.x;
    __shared__ float ps[NE];
    if (tid < NE) {
        float v = 0.f;
        for (int b = 0; b < 32; b++) v += d_auxp[b * NE + tid];
        ps[tid] = v;
        out[(size_t)NTOK * D_MODEL + 1 + tid] = (float)d_cnt[tid];
    }
    __syncthreads();
    if (tid == 0) {
        float aux = 0.f;
        for (int e = 0; e < NE; e++)
            aux += ((float)d_cnt[e] * (1.f / (float)NPAIRS)) * (ps[e] * (1.f / (float)NTOK));
        out[(size_t)NTOK * D_MODEL] = (float)NE * aux;
    }
}

// ---------------------------------------------------------------------------
// GEMM1 fused: g = x@wg^T, u = x@wu^T; 2-term fp16 (A split, B single).
// 512 threads, 4x4 warp grid, 32x32 warp tiles, 4-stage pipeline.
// Stage (32KB): Ah(8K) Al(8K) G(8K) U(8K)
// ---------------------------------------------------------------------------
#define G1_STAGES 4
#define G1_STG  32768
#define G1_SMEM (1024 + G1_STAGES * G1_STG)

__device__ __forceinline__ void g1_issue(int tid, const int* plist,
                                         const __half* gw_, const __half* uw_,
                                         int n0, int kt, uint32_t base) {
    const int r = tid >> 2, c = tid & 3;
    const uint32_t sw = SWZ(r, c);
    const size_t aoff = (size_t)(plist[r] >> 1) * (D_MODEL * 2) + kt * 64 + c * 16;
    const size_t boff = (size_t)(n0 + r) * (D_MODEL * 2) + kt * 64 + c * 16;
    cp16(base + sw,         (const char*)d_x_h + aoff);
    cp16(base + 8192 + sw,  (const char*)d_x_l + aoff);
    cp16(base + 16384 + sw, (const char*)gw_ + boff);
    cp16(base + 24576 + sw, (const char*)uw_ + boff);
}

__global__ __launch_bounds__(512, 1) void gemm1_kernel() {
    const int e = blockIdx.z;
    const int cnt = d_cnt[e];
    const int m0 = blockIdx.x * BM;
    if (m0 >= cnt) return;
    const int n0 = blockIdx.y * BN;

    extern __shared__ __align__(128) char smem[];
    const uint32_t sb = smem_u32(smem);
    const int tid = threadIdx.x;
    const int lane = tid & 31;
    const int w = tid >> 5;
    const int wm = w >> 2, wn = w & 3;
    const int rows = min(BM, cnt - m0);

    int* s_plist = (int*)smem;
    if (tid < BM) s_plist[tid] = (tid < rows) ? d_list[e * NTOK + m0 + tid] : 0;
    __syncthreads();

    const __half* gw_ = d_wg + ((size_t)e << 20);
    const __half* uw_ = d_wu + ((size_t)e << 20);

    g1_issue(tid, s_plist, gw_, uw_, n0, 0, sb + 1024);
    CP_COMMIT();
    g1_issue(tid, s_plist, gw_, uw_, n0, 1, sb + 1024 + G1_STG);
    CP_COMMIT();
    g1_issue(tid, s_plist, gw_, uw_, n0, 2, sb + 1024 + 2 * G1_STG);
    CP_COMMIT();

    float dg[2][4][4], du[2][4][4];
#pragma unroll
    for (int i = 0; i < 2; i++)
#pragma unroll
        for (int j = 0; j < 4; j++)
#pragma unroll
            for (int k = 0; k < 4; k++) { dg[i][j][k] = 0.f; du[i][j][k] = 0.f; }

    for (int kt = 0; kt < NKT; kt++) {
        CP_WAIT2();
        __syncthreads();
        if (kt + 3 < NKT)
            g1_issue(tid, s_plist, gw_, uw_, n0,
                     kt + 3, sb + 1024 + ((kt + 3) % G1_STAGES) * G1_STG);
        CP_COMMIT();

        const uint32_t st = sb + 1024 + (kt % G1_STAGES) * G1_STG;
#pragma unroll
        for (int ks = 0; ks < 2; ks++) {
            uint32_t ah[2][4], al[2][4];
#pragma unroll
            for (int i = 0; i < 2; i++) {
                const int row = wm * 32 + i * 16 + (lane & 15);
                const int ch = ks * 2 + (lane >> 4);
                const uint32_t off = SWZ(row, ch);
                ldmA(ah[i], st + off);
                ldmA(al[i], st + 8192 + off);
            }
            uint32_t bg[4][2], bu[4][2];
#pragma unroll
            for (int j = 0; j < 4; j++) {
                const int row = wn * 32 + j * 8 + (lane & 7);
                const int ch = ks * 2 + ((lane >> 3) & 1);
                const uint32_t off = SWZ(row, ch);
                ldmB(bg[j], st + 16384 + off);
                ldmB(bu[j], st + 24576 + off);
            }
#pragma unroll
            for (int i = 0; i < 2; i++)
#pragma unroll
                for (int j = 0; j < 4; j++) mma16816(dg[i][j], ah[i], bg[j]);
#pragma unroll
            for (int i = 0; i < 2; i++)
#pragma unroll
                for (int j = 0; j < 4; j++) mma16816(du[i][j], ah[i], bu[j]);
#pragma unroll
            for (int i = 0; i < 2; i++)
#pragma unroll
                for (int j = 0; j < 4; j++) mma16816(dg[i][j], al[i], bg[j]);
#pragma unroll
            for (int i = 0; i < 2; i++)
#pragma unroll
                for (int j = 0; j < 4; j++) mma16816(du[i][j], al[i], bu[j]);
        }
        __syncthreads();
    }

    // Epilogue: act = silu(g)*u -> fp16 hi/lo
    const int r0 = lane >> 2;
    const int c0 = (lane & 3) * 2;
#pragma unroll
    for (int i = 0; i < 2; i++) {
        const int mA = wm * 32 + i * 16 + r0;
        const int mB = mA + 8;
        const int pidA = s_plist[mA & 127];
        const int pidB = s_plist[mB & 127];
#pragma unroll
        for (int j = 0; j < 4; j++) {
            const int col = n0 + wn * 32 + j * 8 + c0;
            if (mA < rows) {
                const float a0 = silu_mul(dg[i][j][0], du[i][j][0]);
                const float a1 = silu_mul(dg[i][j][1], du[i][j][1]);
                const __half h0 = __float2half(a0);
                const __half h1 = __float2half(a1);
                *(uint32_t*)(d_act_h + (size_t)pidA * D_FF + col) = pack_h(h0, h1);
                *(uint32_t*)(d_act_l + (size_t)pidA * D_FF + col) =
                    pack_h(__float2half(a0 - __half2float(h0)),
                           __float2half(a1 - __half2float(h1)));
            }
            if (mB < rows) {
                const float a0 = silu_mul(dg[i][j][2], du[i][j][2]);
                const float a1 = silu_mul(dg[i][j][3], du[i][j][3]);
                const __half h0 = __float2half(a0);
                const __half h1 = __float2half(a1);
                *(uint32_t*)(d_act_h + (size_t)pidB * D_FF + col) = pack_h(h0, h1);
                *(uint32_t*)(d_act_l + (size_t)pidB * D_FF + col) =
                    pack_h(__float2half(a0 - __half2float(h0)),
                           __float2half(a1 - __half2float(h1)));
            }
        }
    }
}

// ---------------------------------------------------------------------------
// GEMM2: out += w * (act @ wd^T); 2-term fp16. 256 threads, 64x32 warp tiles,
// 4-stage pipeline, 2 CTAs/SM, float2 atomics.
// Stage (24KB): Ah(8K) Al(8K) B(8K)
// ---------------------------------------------------------------------------
#define G2_STAGES 4
#define G2_STG  24576
#define G2_SMEM (1024 + G2_STAGES * G2_STG)

__device__ __forceinline__ void g2_issue(int tid, const int* plist,
                                         const __half* bw, int n0, int kt, uint32_t base) {
#pragma unroll
    for (int q = 0; q < 2; q++) {
        const int id = tid + q * 256;
        const int r = id >> 2, c = id & 3;
        const uint32_t sw = SWZ(r, c);
        const size_t aoff = (size_t)plist[r] * (D_FF * 2) + kt * 64 + c * 16;
        const size_t boff = (size_t)(n0 + r) * (D_FF * 2) + kt * 64 + c * 16;
        cp16(base + sw,         (const char*)d_act_h + aoff);
        cp16(base + 8192 + sw,  (const char*)d_act_l + aoff);
        cp16(base + 16384 + sw, (const char*)bw + boff);
    }
}

__global__ __launch_bounds__(256, 2) void gemm2_kernel(float* __restrict__ out) {
    const int e = blockIdx.z;
    const int cnt = d_cnt[e];
    const int m0 = blockIdx.x * BM;
    if (m0 >= cnt) return;
    const int n0 = blockIdx.y * BN;

    extern __shared__ __align__(128) char smem[];
    const uint32_t sb = smem_u32(smem);
    const int tid = threadIdx.x;
    const int lane = tid & 31;
    const int w = tid >> 5;
    const int wm = w >> 2, wn = w & 3;
    const int rows = min(BM, cnt - m0);

    int* s_plist = (int*)smem;
    if (tid < BM) s_plist[tid] = (tid < rows) ? d_list[e * NTOK + m0 + tid] : 0;
    __syncthreads();

    const __half* bw = d_wd + ((size_t)e << 20);

    g2_issue(tid, s_plist, bw, n0, 0, sb + 1024);
    CP_COMMIT();
    g2_issue(tid, s_plist, bw, n0, 1, sb + 1024 + G2_STG);
    CP_COMMIT();
    g2_issue(tid, s_plist, bw, n0, 2, sb + 1024 + 2 * G2_STG);
    CP_COMMIT();

    float dd[4][4][4];
#pragma unroll
    for (int i = 0; i < 4; i++)
#pragma unroll
        for (int j = 0; j < 4; j++)
#pragma unroll
            for (int k = 0; k < 4; k++) dd[i][j][k] = 0.f;

    for (int kt = 0; kt < NKT; kt++) {
        CP_WAIT2();
        __syncthreads();
        if (kt + 3 < NKT)
            g2_issue(tid, s_plist, bw, n0, kt + 3,
                     sb + 1024 + ((kt + 3) % G2_STAGES) * G2_STG);
        CP_COMMIT();

        const uint32_t st = sb + 1024 + (kt % G2_STAGES) * G2_STG;
#pragma unroll
        for (int ks = 0; ks < 2; ks++) {
            uint32_t ah[4][4], al[4][4];
#pragma unroll
            for (int i = 0; i < 4; i++) {
                const int row = wm * 64 + i * 16 + (lane & 15);
                const int ch = ks * 2 + (lane >> 4);
                const uint32_t off = SWZ(row, ch);
                ldmA(ah[i], st + off);
                ldmA(al[i], st + 8192 + off);
            }
#pragma unroll
            for (int j = 0; j < 4; j++) {
                const int row = wn * 32 + j * 8 + (lane & 7);
                const int ch = ks * 2 + ((lane >> 3) & 1);
                const uint32_t off = SWZ(row, ch);
                uint32_t fb[2];
                ldmB(fb, st + 16384 + off);
#pragma unroll
                for (int i = 0; i < 4; i++) mma16816(dd[i][j], ah[i], fb);
#pragma unroll
                for (int i = 0; i < 4; i++) mma16816(dd[i][j], al[i], fb);
            }
        }
        __syncthreads();
    }

    // Weighted deterministic scatter: float2 atomics (2 adds/element total)
    const int r0 = lane >> 2;
    const int c0 = (lane & 3) * 2;
#pragma unroll
    for (int i = 0; i < 4; i++) {
        const int mA = wm * 64 + i * 16 + r0;
        const int mB = mA + 8;
        const int pidA = s_plist[mA & 127];
        const int pidB = s_plist[mB & 127];
        const float wA = d_wgt[pidA];
        const float wB = d_wgt[pidB];
#pragma unroll
        for (int j = 0; j < 4; j++) {
            const int col = n0 + wn * 32 + j * 8 + c0;
            if (mA < rows) {
                float2* p = (float2*)(out + (size_t)(pidA >> 1) * D_MODEL + col);
                atomicAdd(p, make_float2(wA * dd[i][j][0], wA * dd[i][j][1]));
            }
            if (mB < rows) {
                float2* p = (float2*)(out + (size_t)(pidB >> 1) * D_MODEL + col);
                atomicAdd(p, make_float2(wB * dd[i][j][2], wB * dd[i][j][3]));
            }
        }
    }
}

// ---------------------------------------------------------------------------
// Launch
// ---------------------------------------------------------------------------
extern "C" void kernel_launch(void* const* d_in, const int* in_sizes, int n_in,
                              void* d_out, int out_size) {
    const float* x  = (const float*)d_in[0];
    const float* gw = (const float*)d_in[1];
    const float* wg = (const float*)d_in[2];
    const float* wu = (const float*)d_in[3];
    const float* wd = (const float*)d_in[4];
    float* out = (float*)d_out;

    cudaFuncSetAttribute(gemm1_kernel, cudaFuncAttributeMaxDynamicSharedMemorySize, G1_SMEM);
    cudaFuncSetAttribute(gemm2_kernel, cudaFuncAttributeMaxDynamicSharedMemorySize, G2_SMEM);

    ConvArgs ca;
    ca.src[0] = x;  ca.src[1] = wg; ca.src[2] = wu; ca.src[3] = wd;
    cudaGetSymbolAddress((void**)&ca.hi[0], d_x_h);
    cudaGetSymbolAddress((void**)&ca.hi[1], d_wg);
    cudaGetSymbolAddress((void**)&ca.hi[2], d_wu);
    cudaGetSymbolAddress((void**)&ca.hi[3], d_wd);
    cudaGetSymbolAddress((void**)&ca.lo, d_x_l);

    init_kernel<<<2048, 256>>>(out);
    conv4_kernel<<<4736, 256>>>(ca);
    router_kernel<<<NTOK / 8, 256>>>(x, gw);
    aux_part_kernel<<<32, 256>>>();
    aux_fin_kernel<<<1, 64>>>(out);
    gemm1_kernel<<<dim3(64, 8, 8), 512, G1_SMEM>>>();
    gemm2_kernel<<<dim3(64, 8, 8), 256, G2_SMEM>>>(out);
}

// round 10
// speedup vs baseline: 6.3268x; 1.5706x over previous
#include <cuda_runtime.h>
#include <cuda_fp16.h>
#include <math.h>
#include <stdint.h>

#define D_MODEL 1024
#define D_FF    1024
#define NE      8
#define NTOK    8192
#define NPAIRS  16384
#define BM      128
#define BN      128
#define NKT     32

// ---------------------------------------------------------------------------
// Static scratch (single fp16 everywhere)
// ---------------------------------------------------------------------------
__device__ __half d_x[(size_t)NTOK * D_MODEL];
__device__ __half d_wg[(size_t)NE * D_FF * D_MODEL];
__device__ __half d_wu[(size_t)NE * D_FF * D_MODEL];
__device__ __half d_wd[(size_t)NE * D_MODEL * D_FF];
__device__ __half d_act[(size_t)NPAIRS * D_FF];
__device__ int   d_list[NE * NTOK];
__device__ int   d_cnt[NE];
__device__ float d_wgt[NPAIRS];
__device__ float d_probs[NTOK * NE];
__device__ float d_auxp[32 * NE];

// ---------------------------------------------------------------------------
// Helpers (generic PTX only)
// ---------------------------------------------------------------------------
__device__ __forceinline__ uint32_t smem_u32(const void* p) {
    uint32_t a;
    asm("{ .reg .u64 t; cvta.to.shared.u64 t, %1; cvt.u32.u64 %0, t; }" : "=r"(a) : "l"(p));
    return a;
}
__device__ __forceinline__ void cp16(uint32_t dst, const void* src) {
    asm volatile("cp.async.cg.shared.global [%0], [%1], 16;" :: "r"(dst), "l"(src));
}
#define CP_COMMIT() asm volatile("cp.async.commit_group;" ::: "memory")
#define CP_WAIT2()  asm volatile("cp.async.wait_group 2;" ::: "memory")

// Conflict-free swizzle for 64B rows of 16B chunks.
#define SWZ(r, c) ((uint32_t)((r) * 64 + (((c) ^ (((r) >> 1) & 3)) << 4)))

__device__ __forceinline__ void ldmA(uint32_t r[4], uint32_t addr) {
    asm volatile("ldmatrix.sync.aligned.m8n8.x4.shared.b16 {%0,%1,%2,%3}, [%4];"
                 : "=r"(r[0]), "=r"(r[1]), "=r"(r[2]), "=r"(r[3]) : "r"(addr));
}
__device__ __forceinline__ void ldmB(uint32_t r[2], uint32_t addr) {
    asm volatile("ldmatrix.sync.aligned.m8n8.x2.shared.b16 {%0,%1}, [%2];"
                 : "=r"(r[0]), "=r"(r[1]) : "r"(addr));
}
__device__ __forceinline__ void mma16816(float d[4], const uint32_t a[4], const uint32_t b[2]) {
    asm volatile("mma.sync.aligned.m16n8k16.row.col.f32.f16.f16.f32 "
                 "{%0,%1,%2,%3}, {%4,%5,%6,%7}, {%8,%9}, {%0,%1,%2,%3};"
                 : "+f"(d[0]), "+f"(d[1]), "+f"(d[2]), "+f"(d[3])
                 : "r"(a[0]), "r"(a[1]), "r"(a[2]), "r"(a[3]), "r"(b[0]), "r"(b[1]));
}
__device__ __forceinline__ uint32_t pack_h(__half a, __half b) {
    return (uint32_t)__half_as_ushort(a) | ((uint32_t)__half_as_ushort(b) << 16);
}
__device__ __forceinline__ float silu_mul(float g, float u) {
    return (g / (1.f + __expf(-g))) * u;
}

// ---------------------------------------------------------------------------
// Init: zero counters + output region
// ---------------------------------------------------------------------------
__global__ void init_kernel(float* __restrict__ out) {
    int idx = blockIdx.x * blockDim.x + threadIdx.x;
    if (idx < NE) d_cnt[idx] = 0;
    float4 z = make_float4(0.f, 0.f, 0.f, 0.f);
    float4* o4 = (float4*)out;
    const int n4 = NTOK * D_MODEL / 4;
    for (int i = idx; i < n4; i += gridDim.x * blockDim.x) o4[i] = z;
}

// ---------------------------------------------------------------------------
// Conversion: 4 regions of exactly 2^21 float4s -> fp16
// ---------------------------------------------------------------------------
struct ConvArgs {
    const float* src[4];
    __half* dst[4];
};

__global__ void conv4_kernel(ConvArgs a) {
    const int total = 4 << 21;
    for (int i = blockIdx.x * blockDim.x + threadIdx.x; i < total; i += gridDim.x * blockDim.x) {
        const int reg = i >> 21;
        const int off = i & ((1 << 21) - 1);
        float4 v = ((const float4*)a.src[reg])[off];
        uint32_t* h2 = (uint32_t*)a.dst[reg];
        h2[2 * off + 0] = pack_h(__float2half(v.x), __float2half(v.y));
        h2[2 * off + 1] = pack_h(__float2half(v.z), __float2half(v.w));
    }
}

// ---------------------------------------------------------------------------
// Router (verbatim — passed since R1)
// ---------------------------------------------------------------------------
__global__ void router_kernel(const float* __restrict__ x, const float* __restrict__ gw) {
    const int lane = threadIdx.x & 31;
    const int warp = threadIdx.x >> 5;
    const int t = blockIdx.x * (blockDim.x >> 5) + warp;
    if (t >= NTOK) return;

    const float4* xp = (const float4*)(x + (size_t)t * D_MODEL);
    float4 xv[8];
#pragma unroll
    for (int i = 0; i < 8; i++) xv[i] = xp[i * 32 + lane];

    float logit[NE];
#pragma unroll
    for (int e = 0; e < NE; e++) {
        const float4* gp = (const float4*)(gw + e * D_MODEL);
        float s = 0.f;
#pragma unroll
        for (int i = 0; i < 8; i++) {
            float4 g = gp[i * 32 + lane];
            s += xv[i].x * g.x + xv[i].y * g.y + xv[i].z * g.z + xv[i].w * g.w;
        }
#pragma unroll
        for (int o = 16; o > 0; o >>= 1) s += __shfl_xor_sync(0xffffffffu, s, o);
        logit[e] = s;
    }

    if (lane == 0) {
        float m = logit[0];
#pragma unroll
        for (int e = 1; e < NE; e++) m = fmaxf(m, logit[e]);
        float p[NE], sum = 0.f;
#pragma unroll
        for (int e = 0; e < NE; e++) { p[e] = expf(logit[e] - m); sum += p[e]; }
        const float inv = 1.f / sum;
#pragma unroll
        for (int e = 0; e < NE; e++) { p[e] *= inv; d_probs[t * NE + e] = p[e]; }

        int i0 = 0;
#pragma unroll
        for (int e = 1; e < NE; e++) if (p[e] > p[i0]) i0 = e;
        int i1 = (i0 == 0) ? 1 : 0;
#pragma unroll
        for (int e = 0; e < NE; e++) if (e != i0 && p[e] > p[i1]) i1 = e;

        const float s2 = p[i0] + p[i1];
        int pos0 = atomicAdd(&d_cnt[i0], 1);
        d_list[i0 * NTOK + pos0] = 2 * t;
        d_wgt[2 * t] = p[i0] / s2;
        int pos1 = atomicAdd(&d_cnt[i1], 1);
        d_list[i1 * NTOK + pos1] = 2 * t + 1;
        d_wgt[2 * t + 1] = p[i1] / s2;
    }
}

// ---------------------------------------------------------------------------
// Aux loss: 32-block partials + finalize (fixed-order, deterministic)
// ---------------------------------------------------------------------------
__global__ void aux_part_kernel() {
    __shared__ float s[256][NE];
    const int tid = threadIdx.x;
    const int t = blockIdx.x * 256 + tid;
#pragma unroll
    for (int e = 0; e < NE; e++) s[tid][e] = d_probs[t * NE + e];
    __syncthreads();
    const int w = tid >> 5, lane = tid & 31;
    if (w < NE) {
        float v = 0.f;
        for (int i = lane; i < 256; i += 32) v += s[i][w];
#pragma unroll
        for (int o = 16; o > 0; o >>= 1) v += __shfl_xor_sync(0xffffffffu, v, o);
        if (lane == 0) d_auxp[blockIdx.x * NE + w] = v;
    }
}

__global__ void aux_fin_kernel(float* __restrict__ out) {
    const int tid = threadIdx.x;
    __shared__ float ps[NE];
    if (tid < NE) {
        float v = 0.f;
        for (int b = 0; b < 32; b++) v += d_auxp[b * NE + tid];
        ps[tid] = v;
        out[(size_t)NTOK * D_MODEL + 1 + tid] = (float)d_cnt[tid];
    }
    __syncthreads();
    if (tid == 0) {
        float aux = 0.f;
        for (int e = 0; e < NE; e++)
            aux += ((float)d_cnt[e] * (1.f / (float)NPAIRS)) * (ps[e] * (1.f / (float)NTOK));
        out[(size_t)NTOK * D_MODEL] = (float)NE * aux;
    }
}

// ---------------------------------------------------------------------------
// GEMM1 fused: g = x@wg^T, u = x@wu^T; single fp16; act = silu(g)*u.
// 512 threads, 4x4 warp grid, 32x32 warp tiles, 4-stage pipeline.
// Stage (24KB): A(8K) G(8K) U(8K)
// ---------------------------------------------------------------------------
#define G1_STAGES 4
#define G1_STG  24576
#define G1_SMEM (1024 + G1_STAGES * G1_STG)

__device__ __forceinline__ void g1_issue(int tid, const int* plist,
                                         const __half* gw_, const __half* uw_,
                                         int n0, int kt, uint32_t base) {
    const int r = tid >> 2, c = tid & 3;
    const uint32_t sw = SWZ(r, c);
    const size_t aoff = (size_t)(plist[r] >> 1) * (D_MODEL * 2) + kt * 64 + c * 16;
    const size_t boff = (size_t)(n0 + r) * (D_MODEL * 2) + kt * 64 + c * 16;
    cp16(base + sw,         (const char*)d_x + aoff);
    cp16(base + 8192 + sw,  (const char*)gw_ + boff);
    cp16(base + 16384 + sw, (const char*)uw_ + boff);
}

__global__ __launch_bounds__(512, 1) void gemm1_kernel() {
    const int e = blockIdx.z;
    const int cnt = d_cnt[e];
    const int m0 = blockIdx.x * BM;
    if (m0 >= cnt) return;
    const int n0 = blockIdx.y * BN;

    extern __shared__ __align__(128) char smem[];
    const uint32_t sb = smem_u32(smem);
    const int tid = threadIdx.x;
    const int lane = tid & 31;
    const int w = tid >> 5;
    const int wm = w >> 2, wn = w & 3;
    const int rows = min(BM, cnt - m0);

    int* s_plist = (int*)smem;
    if (tid < BM) s_plist[tid] = (tid < rows) ? d_list[e * NTOK + m0 + tid] : 0;
    __syncthreads();

    const __half* gw_ = d_wg + ((size_t)e << 20);
    const __half* uw_ = d_wu + ((size_t)e << 20);

    g1_issue(tid, s_plist, gw_, uw_, n0, 0, sb + 1024);
    CP_COMMIT();
    g1_issue(tid, s_plist, gw_, uw_, n0, 1, sb + 1024 + G1_STG);
    CP_COMMIT();
    g1_issue(tid, s_plist, gw_, uw_, n0, 2, sb + 1024 + 2 * G1_STG);
    CP_COMMIT();

    float dg[2][4][4], du[2][4][4];
#pragma unroll
    for (int i = 0; i < 2; i++)
#pragma unroll
        for (int j = 0; j < 4; j++)
#pragma unroll
            for (int k = 0; k < 4; k++) { dg[i][j][k] = 0.f; du[i][j][k] = 0.f; }

    for (int kt = 0; kt < NKT; kt++) {
        CP_WAIT2();
        __syncthreads();
        if (kt + 3 < NKT)
            g1_issue(tid, s_plist, gw_, uw_, n0,
                     kt + 3, sb + 1024 + ((kt + 3) % G1_STAGES) * G1_STG);
        CP_COMMIT();

        const uint32_t st = sb + 1024 + (kt % G1_STAGES) * G1_STG;
#pragma unroll
        for (int ks = 0; ks < 2; ks++) {
            uint32_t ah[2][4];
#pragma unroll
            for (int i = 0; i < 2; i++) {
                const int row = wm * 32 + i * 16 + (lane & 15);
                const int ch = ks * 2 + (lane >> 4);
                ldmA(ah[i], st + SWZ(row, ch));
            }
            uint32_t bg[4][2], bu[4][2];
#pragma unroll
            for (int j = 0; j < 4; j++) {
                const int row = wn * 32 + j * 8 + (lane & 7);
                const int ch = ks * 2 + ((lane >> 3) & 1);
                const uint32_t off = SWZ(row, ch);
                ldmB(bg[j], st + 8192 + off);
                ldmB(bu[j], st + 16384 + off);
            }
#pragma unroll
            for (int i = 0; i < 2; i++)
#pragma unroll
                for (int j = 0; j < 4; j++) mma16816(dg[i][j], ah[i], bg[j]);
#pragma unroll
            for (int i = 0; i < 2; i++)
#pragma unroll
                for (int j = 0; j < 4; j++) mma16816(du[i][j], ah[i], bu[j]);
        }
        __syncthreads();
    }

    // Epilogue: act = silu(g)*u -> fp16
    const int r0 = lane >> 2;
    const int c0 = (lane & 3) * 2;
#pragma unroll
    for (int i = 0; i < 2; i++) {
        const int mA = wm * 32 + i * 16 + r0;
        const int mB = mA + 8;
        const int pidA = s_plist[mA & 127];
        const int pidB = s_plist[mB & 127];
#pragma unroll
        for (int j = 0; j < 4; j++) {
            const int col = n0 + wn * 32 + j * 8 + c0;
            if (mA < rows) {
                *(uint32_t*)(d_act + (size_t)pidA * D_FF + col) =
                    pack_h(__float2half(silu_mul(dg[i][j][0], du[i][j][0])),
                           __float2half(silu_mul(dg[i][j][1], du[i][j][1])));
            }
            if (mB < rows) {
                *(uint32_t*)(d_act + (size_t)pidB * D_FF + col) =
                    pack_h(__float2half(silu_mul(dg[i][j][2], du[i][j][2])),
                           __float2half(silu_mul(dg[i][j][3], du[i][j][3])));
            }
        }
    }
}

// ---------------------------------------------------------------------------
// GEMM2: out += w * (act @ wd^T); single fp16. 256 threads, 64x32 warp tiles,
// 4-stage pipeline, 2 CTAs/SM, float2 atomics.
// Stage (16KB): A(8K) B(8K)
// ---------------------------------------------------------------------------
#define G2_STAGES 4
#define G2_STG  16384
#define G2_SMEM (1024 + G2_STAGES * G2_STG)

__device__ __forceinline__ void g2_issue(int tid, const int* plist,
                                         const __half* bw, int n0, int kt, uint32_t base) {
#pragma unroll
    for (int q = 0; q < 2; q++) {
        const int id = tid + q * 256;
        const int r = id >> 2, c = id & 3;
        const uint32_t sw = SWZ(r, c);
        const size_t aoff = (size_t)plist[r] * (D_FF * 2) + kt * 64 + c * 16;
        const size_t boff = (size_t)(n0 + r) * (D_FF * 2) + kt * 64 + c * 16;
        cp16(base + sw,        (const char*)d_act + aoff);
        cp16(base + 8192 + sw, (const char*)bw + boff);
    }
}

__global__ __launch_bounds__(256, 2) void gemm2_kernel(float* __restrict__ out) {
    const int e = blockIdx.z;
    const int cnt = d_cnt[e];
    const int m0 = blockIdx.x * BM;
    if (m0 >= cnt) return;
    const int n0 = blockIdx.y * BN;

    extern __shared__ __align__(128) char smem[];
    const uint32_t sb = smem_u32(smem);
    const int tid = threadIdx.x;
    const int lane = tid & 31;
    const int w = tid >> 5;
    const int wm = w >> 2, wn = w & 3;
    const int rows = min(BM, cnt - m0);

    int* s_plist = (int*)smem;
    if (tid < BM) s_plist[tid] = (tid < rows) ? d_list[e * NTOK + m0 + tid] : 0;
    __syncthreads();

    const __half* bw = d_wd + ((size_t)e << 20);

    g2_issue(tid, s_plist, bw, n0, 0, sb + 1024);
    CP_COMMIT();
    g2_issue(tid, s_plist, bw, n0, 1, sb + 1024 + G2_STG);
    CP_COMMIT();
    g2_issue(tid, s_plist, bw, n0, 2, sb + 1024 + 2 * G2_STG);
    CP_COMMIT();

    float dd[4][4][4];
#pragma unroll
    for (int i = 0; i < 4; i++)
#pragma unroll
        for (int j = 0; j < 4; j++)
#pragma unroll
            for (int k = 0; k < 4; k++) dd[i][j][k] = 0.f;

    for (int kt = 0; kt < NKT; kt++) {
        CP_WAIT2();
        __syncthreads();
        if (kt + 3 < NKT)
            g2_issue(tid, s_plist, bw, n0, kt + 3,
                     sb + 1024 + ((kt + 3) % G2_STAGES) * G2_STG);
        CP_COMMIT();

        const uint32_t st = sb + 1024 + (kt % G2_STAGES) * G2_STG;
#pragma unroll
        for (int ks = 0; ks < 2; ks++) {
            uint32_t ah[4][4];
#pragma unroll
            for (int i = 0; i < 4; i++) {
                const int row = wm * 64 + i * 16 + (lane & 15);
                const int ch = ks * 2 + (lane >> 4);
                ldmA(ah[i], st + SWZ(row, ch));
            }
#pragma unroll
            for (int j = 0; j < 4; j++) {
                const int row = wn * 32 + j * 8 + (lane & 7);
                const int ch = ks * 2 + ((lane >> 3) & 1);
                uint32_t fb[2];
                ldmB(fb, st + 8192 + SWZ(row, ch));
#pragma unroll
                for (int i = 0; i < 4; i++) mma16816(dd[i][j], ah[i], fb);
            }
        }
        __syncthreads();
    }

    // Weighted deterministic scatter: float2 atomics (2 adds/element total)
    const int r0 = lane >> 2;
    const int c0 = (lane & 3) * 2;
#pragma unroll
    for (int i = 0; i < 4; i++) {
        const int mA = wm * 64 + i * 16 + r0;
        const int mB = mA + 8;
        const int pidA = s_plist[mA & 127];
        const int pidB = s_plist[mB & 127];
        const float wA = d_wgt[pidA];
        const float wB = d_wgt[pidB];
#pragma unroll
        for (int j = 0; j < 4; j++) {
            const int col = n0 + wn * 32 + j * 8 + c0;
            if (mA < rows) {
                float2* p = (float2*)(out + (size_t)(pidA >> 1) * D_MODEL + col);
                atomicAdd(p, make_float2(wA * dd[i][j][0], wA * dd[i][j][1]));
            }
            if (mB < rows) {
                float2* p = (float2*)(out + (size_t)(pidB >> 1) * D_MODEL + col);
                atomicAdd(p, make_float2(wB * dd[i][j][2], wB * dd[i][j][3]));
            }
        }
    }
}

// ---------------------------------------------------------------------------
// Launch
// ---------------------------------------------------------------------------
extern "C" void kernel_launch(void* const* d_in, const int* in_sizes, int n_in,
                              void* d_out, int out_size) {
    const float* x  = (const float*)d_in[0];
    const float* gw = (const float*)d_in[1];
    const float* wg = (const float*)d_in[2];
    const float* wu = (const float*)d_in[3];
    const float* wd = (const float*)d_in[4];
    float* out = (float*)d_out;

    cudaFuncSetAttribute(gemm1_kernel, cudaFuncAttributeMaxDynamicSharedMemorySize, G1_SMEM);
    cudaFuncSetAttribute(gemm2_kernel, cudaFuncAttributeMaxDynamicSharedMemorySize, G2_SMEM);

    ConvArgs ca;
    ca.src[0] = x;  ca.src[1] = wg; ca.src[2] = wu; ca.src[3] = wd;
    cudaGetSymbolAddress((void**)&ca.dst[0], d_x);
    cudaGetSymbolAddress((void**)&ca.dst[1], d_wg);
    cudaGetSymbolAddress((void**)&ca.dst[2], d_wu);
    cudaGetSymbolAddress((void**)&ca.dst[3], d_wd);

    init_kernel<<<2048, 256>>>(out);
    conv4_kernel<<<4736, 256>>>(ca);
    router_kernel<<<NTOK / 8, 256>>>(x, gw);
    aux_part_kernel<<<32, 256>>>();
    aux_fin_kernel<<<1, 64>>>(out);
    gemm1_kernel<<<dim3(64, 8, 8), 512, G1_SMEM>>>();
    gemm2_kernel<<<dim3(64, 8, 8), 256, G2_SMEM>>>(out);
}